// round 8
// baseline (speedup 1.0000x reference)
#include <cuda_runtime.h>
#include <math.h>
#include <stdint.h>

#define B_  8
#define T_  1024
#define E_  1024
#define H_  16
#define DH_ 64

// Scratch (__device__ globals: allocation-free rule)
__device__ float g_qkv[(size_t)B_ * T_ * 3 * E_];  // 96 MB
__device__ float g_att[(size_t)B_ * T_ * E_];      // 32 MB
__device__ float g_p1 [(size_t)B_ * T_ * E_];      // 32 MB
__device__ float g_wi [(size_t)3 * E_ * E_];       // rounded weights
__device__ float g_wo [(size_t)E_ * E_];
__device__ float g_wc [(size_t)E_ * E_];

// ---------------------------------------------------------------------------
__device__ __forceinline__ float tf32r(float x) {
    uint32_t u;
    asm("cvt.rna.tf32.f32 %0, %1;" : "=r"(u) : "f"(x));
    return __uint_as_float(u);
}
__device__ __forceinline__ uint32_t sptr(const void* p) {
    return (uint32_t)__cvta_generic_to_shared(p);
}
__device__ __forceinline__ void cpa16(uint32_t dst, const float* src) {
    asm volatile("cp.async.cg.shared.global [%0], [%1], 16;\n" :: "r"(dst), "l"(src));
}
__device__ __forceinline__ void mma_tf32(
    float& c0, float& c1, float& c2, float& c3,
    uint32_t a0, uint32_t a1, uint32_t a2, uint32_t a3,
    uint32_t b0, uint32_t b1)
{
    asm volatile(
        "mma.sync.aligned.m16n8k8.row.col.f32.tf32.tf32.f32 "
        "{%0,%1,%2,%3},{%4,%5,%6,%7},{%8,%9},{%0,%1,%2,%3};"
        : "+f"(c0), "+f"(c1), "+f"(c2), "+f"(c3)
        : "r"(a0), "r"(a1), "r"(a2), "r"(a3), "r"(b0), "r"(b1));
}

// round weights to tf32 grid (rna, unbiased) ---------------------------------
__global__ void __launch_bounds__(256) cvt_w(const float* __restrict__ wi,
                                             const float* __restrict__ wo,
                                             const float* __restrict__ wc) {
    int i = blockIdx.x * blockDim.x + threadIdx.x;
    const int n_i = 3 * E_ * E_ / 4;
    const int n_o = E_ * E_ / 4;
    const float4* src;
    float4* dst;
    int j;
    if (i < n_i)                 { src = (const float4*)wi; dst = (float4*)g_wi; j = i; }
    else if (i < n_i + n_o)      { src = (const float4*)wo; dst = (float4*)g_wo; j = i - n_i; }
    else if (i < n_i + 2 * n_o)  { src = (const float4*)wc; dst = (float4*)g_wc; j = i - n_i - n_o; }
    else return;
    float4 v = src[j];
    v.x = tf32r(v.x); v.y = tf32r(v.y); v.z = tf32r(v.z); v.w = tf32r(v.w);
    dst[j] = v;
}

// ---------------------------------------------------------------------------
// TF32 tensor-core GEMM: C[M,N] = A[M,K] @ B[N,K]^T + bias[N]
// 128x128 CTA tile, BK=16, 8 warps 2x4, warp tile 64x32.
// 2-stage cp.async pipeline, ONE __syncthreads per K-step:
//   top of iter: wait(tile it) ; sync (also proves compute it-1 done)
//   -> issue tile it+1 into the freed buffer ; compute tile it.
// Static smem 2*2*128*20*4 = 40960 bytes.
// ---------------------------------------------------------------------------
__device__ __forceinline__ void gemm_tf32_body(
    const float* __restrict__ A, const float* __restrict__ Bm,
    const float* __restrict__ bias, float* __restrict__ C,
    int N, int K, int round_a, int round_out)
{
    __shared__ float As[2][128][20];
    __shared__ float Bs[2][128][20];

    const int tid  = threadIdx.x;
    const int lane = tid & 31;
    const int wid  = tid >> 5;
    const int gid  = lane >> 2;
    const int tig  = lane & 3;
    const int wm   = (wid >> 2) * 64;
    const int wn   = (wid & 3) * 32;
    const int bm   = blockIdx.y * 128;
    const int bn   = blockIdx.x * 128;

    float acc[4][4][4];
#pragma unroll
    for (int mt = 0; mt < 4; mt++)
#pragma unroll
        for (int nt = 0; nt < 4; nt++)
#pragma unroll
            for (int r = 0; r < 4; r++) acc[mt][nt][r] = 0.f;

    auto issue = [&](int k0, int s) {
#pragma unroll
        for (int i = 0; i < 2; i++) {
            int idx = tid + i * 256;
            int row = idx >> 2;
            int c4  = (idx & 3) << 2;
            cpa16(sptr(&As[s][row][c4]), A  + (size_t)(bm + row) * K + k0 + c4);
            cpa16(sptr(&Bs[s][row][c4]), Bm + (size_t)(bn + row) * K + k0 + c4);
        }
    };

    issue(0, 0);
    asm volatile("cp.async.commit_group;\n" ::: "memory");

    const int NIT = K / 16;
    for (int it = 0; it < NIT; it++) {
        asm volatile("cp.async.wait_group 0;\n" ::: "memory");  // tile it ready
        __syncthreads();            // + all warps done computing tile it-1
        if (it + 1 < NIT) {         // prefetch overlaps the compute below
            issue((it + 1) * 16, (it + 1) & 1);
            asm volatile("cp.async.commit_group;\n" ::: "memory");
        }

        const int s = it & 1;
#pragma unroll
        for (int ks = 0; ks < 2; ks++) {
            const int kk = ks * 8 + tig;
            uint32_t a[4][4], b[4][2];
#pragma unroll
            for (int mt = 0; mt < 4; mt++) {
                int r0 = wm + mt * 16 + gid;
                float a0 = As[s][r0    ][kk    ];
                float a1 = As[s][r0 + 8][kk    ];
                float a2 = As[s][r0    ][kk + 4];
                float a3 = As[s][r0 + 8][kk + 4];
                if (round_a) { a0 = tf32r(a0); a1 = tf32r(a1); a2 = tf32r(a2); a3 = tf32r(a3); }
                a[mt][0] = __float_as_uint(a0);
                a[mt][1] = __float_as_uint(a1);
                a[mt][2] = __float_as_uint(a2);
                a[mt][3] = __float_as_uint(a3);
            }
#pragma unroll
            for (int nt = 0; nt < 4; nt++) {
                int c0i = wn + nt * 8 + gid;
                b[nt][0] = __float_as_uint(Bs[s][c0i][kk    ]);
                b[nt][1] = __float_as_uint(Bs[s][c0i][kk + 4]);
            }
#pragma unroll
            for (int mt = 0; mt < 4; mt++)
#pragma unroll
                for (int nt = 0; nt < 4; nt++)
                    mma_tf32(acc[mt][nt][0], acc[mt][nt][1], acc[mt][nt][2], acc[mt][nt][3],
                             a[mt][0], a[mt][1], a[mt][2], a[mt][3], b[nt][0], b[nt][1]);
        }
    }

#pragma unroll
    for (int mt = 0; mt < 4; mt++) {
#pragma unroll
        for (int nt = 0; nt < 4; nt++) {
            int row = bm + wm + mt * 16 + gid;
            int col = bn + wn + nt * 8 + tig * 2;
            float bv0 = bias[col], bv1 = bias[col + 1];
            float v0 = acc[mt][nt][0] + bv0;
            float v1 = acc[mt][nt][1] + bv1;
            float v2 = acc[mt][nt][2] + bv0;
            float v3 = acc[mt][nt][3] + bv1;
            if (round_out) {
                v0 = tf32r(v0); v1 = tf32r(v1); v2 = tf32r(v2); v3 = tf32r(v3);
            }
            *reinterpret_cast<float2*>(C + (size_t)row * N + col) = make_float2(v0, v1);
            *reinterpret_cast<float2*>(C + (size_t)(row + 8) * N + col) = make_float2(v2, v3);
        }
    }
}

__global__ void __launch_bounds__(256, 2) gemm_in_x(const float* __restrict__ x,
                                                    const float* __restrict__ bi) {
    gemm_tf32_body(x, g_wi, bi, g_qkv, 3 * E_, E_, 1, 1);   // round A in-register
}
__global__ void __launch_bounds__(256, 2) gemm_out_k(const float* __restrict__ bo) {
    gemm_tf32_body(g_att, g_wo, bo, g_p1, E_, E_, 0, 1);
}
__global__ void __launch_bounds__(256, 2) gemm_c_k(const float* __restrict__ bc,
                                                   float* __restrict__ out) {
    gemm_tf32_body(g_p1, g_wc, bc, out, E_, E_, 0, 0);
}

// ---------------------------------------------------------------------------
// Tensor-core causal flash attention (tf32 MMA, fp32 softmax) — R5 version.
// grid (T/64, B*H), 128 threads (4 warps), warp = 16 query rows.
// KV tile = 64. K smem [key][d-interleaved], V smem transposed [d][key-ilv]
// with XOR swizzle f(d)=((d>>2)&3)<<1. Static smem 36 KB.
// ---------------------------------------------------------------------------
#define ST_ 72
__device__ __forceinline__ int ilv8(int o) {   // 0..7 -> 0,2,4,6,1,3,5,7
    return ((o & 3) << 1) | ((o >> 2) & 1);
}

__global__ void __launch_bounds__(128, 3) flash_attn()
{
    __shared__ __align__(16) float sm0[64 * ST_];  // Q, then K tiles
    __shared__ __align__(16) float sm1[64 * ST_];  // V^T tiles

    const float* qkv = g_qkv;
    const int tid  = threadIdx.x;
    const int lane = tid & 31;
    const int w    = tid >> 5;
    const int gid  = lane >> 2;
    const int tig  = lane & 3;
    const int qb   = blockIdx.x;
    const int b    = blockIdx.y >> 4;
    const int h    = blockIdx.y & 15;
    const size_t base = (size_t)b * T_ * 3 * E_ + (size_t)h * DH_;

    // ---- load Q tile (64x64) into sm0, d-interleaved ----
#pragma unroll
    for (int i = 0; i < 8; i++) {
        int idx = tid + i * 128;              // 0..1023
        int row = idx >> 4;
        int d4  = (idx & 15) << 2;
        float4 v = *reinterpret_cast<const float4*>(
            qkv + base + (size_t)(qb * 64 + row) * 3 * E_ + d4);
        int bp = (d4 & ~7) | ((d4 >> 2) & 1);
        sm0[row * ST_ + bp    ] = v.x;
        sm0[row * ST_ + bp + 2] = v.y;
        sm0[row * ST_ + bp + 4] = v.z;
        sm0[row * ST_ + bp + 6] = v.w;
    }
    __syncthreads();

    // ---- Q fragments to registers (scale 1/8 folded: exact pow2) ----
    uint32_t qf[8][4];
    {
        const int r0 = w * 16 + gid;
#pragma unroll
        for (int kc = 0; kc < 8; kc++) {
            float2 t0 = *reinterpret_cast<const float2*>(&sm0[ r0      * ST_ + kc * 8 + 2 * tig]);
            float2 t1 = *reinterpret_cast<const float2*>(&sm0[(r0 + 8) * ST_ + kc * 8 + 2 * tig]);
            qf[kc][0] = __float_as_uint(t0.x * 0.125f);
            qf[kc][1] = __float_as_uint(t1.x * 0.125f);
            qf[kc][2] = __float_as_uint(t0.y * 0.125f);
            qf[kc][3] = __float_as_uint(t1.y * 0.125f);
        }
    }

    float m0 = -1e30f, m1 = -1e30f, l0 = 0.f, l1 = 0.f;
    float oacc[8][4];
#pragma unroll
    for (int n = 0; n < 8; n++)
#pragma unroll
        for (int r = 0; r < 4; r++) oacc[n][r] = 0.f;

    const int nkb = qb + 1;
    for (int kb = 0; kb < nkb; kb++) {
        __syncthreads();   // prior iter (or Q frag reads) done with sm0/sm1

        // ---- load K (direct, d-interleaved) and V (transposed, swizzled) ----
#pragma unroll
        for (int i = 0; i < 8; i++) {
            int idx = tid + i * 128;
            int row = idx >> 4;               // key 0..63
            int d4  = (idx & 15) << 2;
            size_t tok = (size_t)(kb * 64 + row) * 3 * E_;
            float4 kv4 = *reinterpret_cast<const float4*>(qkv + base + E_ + tok + d4);
            int bp = (d4 & ~7) | ((d4 >> 2) & 1);
            sm0[row * ST_ + bp    ] = kv4.x;
            sm0[row * ST_ + bp + 2] = kv4.y;
            sm0[row * ST_ + bp + 4] = kv4.z;
            sm0[row * ST_ + bp + 6] = kv4.w;
            float4 vv4 = *reinterpret_cast<const float4*>(qkv + base + 2 * E_ + tok + d4);
            int f  = ((d4 >> 2) & 3) << 1;    // same for d4..d4+3
            int pk = (row & ~7) | (ilv8(row & 7) ^ f);
            sm1[(d4 + 0) * ST_ + pk] = vv4.x;
            sm1[(d4 + 1) * ST_ + pk] = vv4.y;
            sm1[(d4 + 2) * ST_ + pk] = vv4.z;
            sm1[(d4 + 3) * ST_ + pk] = vv4.w;
        }
        __syncthreads();

        // ---- S = Q K^T ----
        float sacc[8][4];
#pragma unroll
        for (int n = 0; n < 8; n++)
#pragma unroll
            for (int r = 0; r < 4; r++) sacc[n][r] = 0.f;

#pragma unroll
        for (int kc = 0; kc < 8; kc++)
#pragma unroll
            for (int n = 0; n < 8; n++) {
                float2 bb = *reinterpret_cast<const float2*>(
                    &sm0[(n * 8 + gid) * ST_ + kc * 8 + 2 * tig]);
                mma_tf32(sacc[n][0], sacc[n][1], sacc[n][2], sacc[n][3],
                         qf[kc][0], qf[kc][1], qf[kc][2], qf[kc][3],
                         __float_as_uint(bb.x), __float_as_uint(bb.y));
            }

        // ---- causal mask (diagonal tile only) ----
        if (kb == qb) {
            const int r0 = w * 16 + gid;
#pragma unroll
            for (int n = 0; n < 8; n++) {
                int c = n * 8 + 2 * tig;
                if (c     > r0    ) sacc[n][0] = -1e30f;
                if (c + 1 > r0    ) sacc[n][1] = -1e30f;
                if (c     > r0 + 8) sacc[n][2] = -1e30f;
                if (c + 1 > r0 + 8) sacc[n][3] = -1e30f;
            }
        }

        // ---- online softmax ----
        float mx0 = -1e30f, mx1 = -1e30f;
#pragma unroll
        for (int n = 0; n < 8; n++) {
            mx0 = fmaxf(mx0, fmaxf(sacc[n][0], sacc[n][1]));
            mx1 = fmaxf(mx1, fmaxf(sacc[n][2], sacc[n][3]));
        }
        mx0 = fmaxf(mx0, __shfl_xor_sync(0xffffffffu, mx0, 1));
        mx0 = fmaxf(mx0, __shfl_xor_sync(0xffffffffu, mx0, 2));
        mx1 = fmaxf(mx1, __shfl_xor_sync(0xffffffffu, mx1, 1));
        mx1 = fmaxf(mx1, __shfl_xor_sync(0xffffffffu, mx1, 2));
        float mn0 = fmaxf(m0, mx0), mn1 = fmaxf(m1, mx1);
        float al0 = __expf(m0 - mn0), al1 = __expf(m1 - mn1);
        m0 = mn0; m1 = mn1;

        float sum0 = 0.f, sum1 = 0.f;
#pragma unroll
        for (int n = 0; n < 8; n++) {
            float p0 = tf32r(__expf(sacc[n][0] - mn0));
            float p1 = tf32r(__expf(sacc[n][1] - mn0));
            float p2 = tf32r(__expf(sacc[n][2] - mn1));
            float p3 = tf32r(__expf(sacc[n][3] - mn1));
            sum0 += p0 + p1; sum1 += p2 + p3;
            sacc[n][0] = p0; sacc[n][1] = p1; sacc[n][2] = p2; sacc[n][3] = p3;
        }
        sum0 += __shfl_xor_sync(0xffffffffu, sum0, 1);
        sum0 += __shfl_xor_sync(0xffffffffu, sum0, 2);
        sum1 += __shfl_xor_sync(0xffffffffu, sum1, 1);
        sum1 += __shfl_xor_sync(0xffffffffu, sum1, 2);
        l0 = l0 * al0 + sum0;
        l1 = l1 * al1 + sum1;
#pragma unroll
        for (int n = 0; n < 8; n++) {
            oacc[n][0] *= al0; oacc[n][1] *= al0;
            oacc[n][2] *= al1; oacc[n][3] *= al1;
        }

        // ---- O += P V : shuffle P C-frags -> A-frags, 8 k-chunks ----
        const int src0 = (lane & 28) | (tig >> 1);
        const int src1 = src0 + 2;
        const bool odd = (tig & 1);
#pragma unroll
        for (int kc = 0; kc < 8; kc++) {
            float v00 = __shfl_sync(0xffffffffu, sacc[kc][0], src0);
            float v01 = __shfl_sync(0xffffffffu, sacc[kc][1], src0);
            float v10 = __shfl_sync(0xffffffffu, sacc[kc][0], src1);
            float v11 = __shfl_sync(0xffffffffu, sacc[kc][1], src1);
            float v20 = __shfl_sync(0xffffffffu, sacc[kc][2], src0);
            float v21 = __shfl_sync(0xffffffffu, sacc[kc][3], src0);
            float v30 = __shfl_sync(0xffffffffu, sacc[kc][2], src1);
            float v31 = __shfl_sync(0xffffffffu, sacc[kc][3], src1);
            uint32_t a0 = __float_as_uint(odd ? v01 : v00);
            uint32_t a2 = __float_as_uint(odd ? v11 : v10);
            uint32_t a1 = __float_as_uint(odd ? v21 : v20);
            uint32_t a3 = __float_as_uint(odd ? v31 : v30);
#pragma unroll
            for (int n = 0; n < 8; n++) {
                int rowd = n * 8 + gid;
                int f    = ((rowd >> 2) & 3) << 1;
                float2 vb = *reinterpret_cast<const float2*>(
                    &sm1[rowd * ST_ + kc * 8 + ((2 * tig) ^ f)]);
                mma_tf32(oacc[n][0], oacc[n][1], oacc[n][2], oacc[n][3],
                         a0, a1, a2, a3,
                         __float_as_uint(vb.x), __float_as_uint(vb.y));
            }
        }
    }

    // ---- epilogue: normalize, round to tf32 grid, write [B,T,E] ----
    const float inv0 = 1.f / l0, inv1 = 1.f / l1;
    const int row0 = qb * 64 + w * 16 + gid;
#pragma unroll
    for (int n = 0; n < 8; n++) {
        int col = h * DH_ + n * 8 + 2 * tig;
        size_t o0 = ((size_t)b * T_ + row0) * E_ + col;
        size_t o1 = ((size_t)b * T_ + row0 + 8) * E_ + col;
        *reinterpret_cast<float2*>(g_att + o0) =
            make_float2(tf32r(oacc[n][0] * inv0), tf32r(oacc[n][1] * inv0));
        *reinterpret_cast<float2*>(g_att + o1) =
            make_float2(tf32r(oacc[n][2] * inv1), tf32r(oacc[n][3] * inv1));
    }
}

// ---------------------------------------------------------------------------
extern "C" void kernel_launch(void* const* d_in, const int* in_sizes, int n_in,
                              void* d_out, int out_size)
{
    const float* x  = (const float*)d_in[0];
    const float* wi = (const float*)d_in[1];
    const float* bi = (const float*)d_in[2];
    const float* wo = (const float*)d_in[3];
    const float* bo = (const float*)d_in[4];
    const float* wc = (const float*)d_in[5];
    const float* bc = (const float*)d_in[6];
    float* out = (float*)d_out;

    const int M = B_ * T_;  // 8192

    cvt_w<<<(5 * E_ * E_ / 4 + 255) / 256, 256>>>(wi, wo, wc);
    gemm_in_x<<<dim3(3 * E_ / 128, M / 128), 256>>>(x, bi);
    flash_attn<<<dim3(T_ / 64, B_ * H_), 128>>>();
    gemm_out_k<<<dim3(E_ / 128, M / 128), 256>>>(bo);
    gemm_c_k<<<dim3(E_ / 128, M / 128), 256>>>(bc, out);
}

// round 9
// speedup vs baseline: 1.0870x; 1.0870x over previous
#include <cuda_runtime.h>
#include <math.h>
#include <stdint.h>

#define B_  8
#define T_  1024
#define E_  1024
#define H_  16
#define DH_ 64

// Scratch (__device__ globals: allocation-free rule)
__device__ float g_qkv[(size_t)B_ * T_ * 3 * E_];  // 96 MB
__device__ float g_att[(size_t)B_ * T_ * E_];      // 32 MB
__device__ float g_p1 [(size_t)B_ * T_ * E_];      // 32 MB
__device__ float g_wi [(size_t)3 * E_ * E_];       // rounded weights
__device__ float g_wo [(size_t)E_ * E_];
__device__ float g_wc [(size_t)E_ * E_];

// ---------------------------------------------------------------------------
__device__ __forceinline__ float tf32r(float x) {
    uint32_t u;
    asm("cvt.rna.tf32.f32 %0, %1;" : "=r"(u) : "f"(x));
    return __uint_as_float(u);
}
__device__ __forceinline__ uint32_t sptr(const void* p) {
    return (uint32_t)__cvta_generic_to_shared(p);
}
__device__ __forceinline__ void cpa16(uint32_t dst, const float* src) {
    asm volatile("cp.async.cg.shared.global [%0], [%1], 16;\n" :: "r"(dst), "l"(src));
}
__device__ __forceinline__ void mma_tf32(
    float& c0, float& c1, float& c2, float& c3,
    uint32_t a0, uint32_t a1, uint32_t a2, uint32_t a3,
    uint32_t b0, uint32_t b1)
{
    asm volatile(
        "mma.sync.aligned.m16n8k8.row.col.f32.tf32.tf32.f32 "
        "{%0,%1,%2,%3},{%4,%5,%6,%7},{%8,%9},{%0,%1,%2,%3};"
        : "+f"(c0), "+f"(c1), "+f"(c2), "+f"(c3)
        : "r"(a0), "r"(a1), "r"(a2), "r"(a3), "r"(b0), "r"(b1));
}

// round weights to tf32 grid (rna, unbiased) ---------------------------------
__global__ void __launch_bounds__(256) cvt_w(const float* __restrict__ wi,
                                             const float* __restrict__ wo,
                                             const float* __restrict__ wc) {
    int i = blockIdx.x * blockDim.x + threadIdx.x;
    const int n_i = 3 * E_ * E_ / 4;
    const int n_o = E_ * E_ / 4;
    const float4* src;
    float4* dst;
    int j;
    if (i < n_i)                 { src = (const float4*)wi; dst = (float4*)g_wi; j = i; }
    else if (i < n_i + n_o)      { src = (const float4*)wo; dst = (float4*)g_wo; j = i - n_i; }
    else if (i < n_i + 2 * n_o)  { src = (const float4*)wc; dst = (float4*)g_wc; j = i - n_i - n_o; }
    else return;
    float4 v = src[j];
    v.x = tf32r(v.x); v.y = tf32r(v.y); v.z = tf32r(v.z); v.w = tf32r(v.w);
    dst[j] = v;
}

// ---------------------------------------------------------------------------
// TF32 tensor-core GEMM (unchanged from R8, passing): 128x128 tile, BK=16,
// 8 warps 2x4, 2-stage cp.async, one __syncthreads per K-step.
// ---------------------------------------------------------------------------
__device__ __forceinline__ void gemm_tf32_body(
    const float* __restrict__ A, const float* __restrict__ Bm,
    const float* __restrict__ bias, float* __restrict__ C,
    int N, int K, int round_a, int round_out)
{
    __shared__ float As[2][128][20];
    __shared__ float Bs[2][128][20];

    const int tid  = threadIdx.x;
    const int lane = tid & 31;
    const int wid  = tid >> 5;
    const int gid  = lane >> 2;
    const int tig  = lane & 3;
    const int wm   = (wid >> 2) * 64;
    const int wn   = (wid & 3) * 32;
    const int bm   = blockIdx.y * 128;
    const int bn   = blockIdx.x * 128;

    float acc[4][4][4];
#pragma unroll
    for (int mt = 0; mt < 4; mt++)
#pragma unroll
        for (int nt = 0; nt < 4; nt++)
#pragma unroll
            for (int r = 0; r < 4; r++) acc[mt][nt][r] = 0.f;

    auto issue = [&](int k0, int s) {
#pragma unroll
        for (int i = 0; i < 2; i++) {
            int idx = tid + i * 256;
            int row = idx >> 2;
            int c4  = (idx & 3) << 2;
            cpa16(sptr(&As[s][row][c4]), A  + (size_t)(bm + row) * K + k0 + c4);
            cpa16(sptr(&Bs[s][row][c4]), Bm + (size_t)(bn + row) * K + k0 + c4);
        }
    };

    issue(0, 0);
    asm volatile("cp.async.commit_group;\n" ::: "memory");

    const int NIT = K / 16;
    for (int it = 0; it < NIT; it++) {
        asm volatile("cp.async.wait_group 0;\n" ::: "memory");
        __syncthreads();
        if (it + 1 < NIT) {
            issue((it + 1) * 16, (it + 1) & 1);
            asm volatile("cp.async.commit_group;\n" ::: "memory");
        }

        const int s = it & 1;
#pragma unroll
        for (int ks = 0; ks < 2; ks++) {
            const int kk = ks * 8 + tig;
            uint32_t a[4][4], b[4][2];
#pragma unroll
            for (int mt = 0; mt < 4; mt++) {
                int r0 = wm + mt * 16 + gid;
                float a0 = As[s][r0    ][kk    ];
                float a1 = As[s][r0 + 8][kk    ];
                float a2 = As[s][r0    ][kk + 4];
                float a3 = As[s][r0 + 8][kk + 4];
                if (round_a) { a0 = tf32r(a0); a1 = tf32r(a1); a2 = tf32r(a2); a3 = tf32r(a3); }
                a[mt][0] = __float_as_uint(a0);
                a[mt][1] = __float_as_uint(a1);
                a[mt][2] = __float_as_uint(a2);
                a[mt][3] = __float_as_uint(a3);
            }
#pragma unroll
            for (int nt = 0; nt < 4; nt++) {
                int c0i = wn + nt * 8 + gid;
                b[nt][0] = __float_as_uint(Bs[s][c0i][kk    ]);
                b[nt][1] = __float_as_uint(Bs[s][c0i][kk + 4]);
            }
#pragma unroll
            for (int mt = 0; mt < 4; mt++)
#pragma unroll
                for (int nt = 0; nt < 4; nt++)
                    mma_tf32(acc[mt][nt][0], acc[mt][nt][1], acc[mt][nt][2], acc[mt][nt][3],
                             a[mt][0], a[mt][1], a[mt][2], a[mt][3], b[nt][0], b[nt][1]);
        }
    }

#pragma unroll
    for (int mt = 0; mt < 4; mt++) {
#pragma unroll
        for (int nt = 0; nt < 4; nt++) {
            int row = bm + wm + mt * 16 + gid;
            int col = bn + wn + nt * 8 + tig * 2;
            float bv0 = bias[col], bv1 = bias[col + 1];
            float v0 = acc[mt][nt][0] + bv0;
            float v1 = acc[mt][nt][1] + bv1;
            float v2 = acc[mt][nt][2] + bv0;
            float v3 = acc[mt][nt][3] + bv1;
            if (round_out) {
                v0 = tf32r(v0); v1 = tf32r(v1); v2 = tf32r(v2); v3 = tf32r(v3);
            }
            *reinterpret_cast<float2*>(C + (size_t)row * N + col) = make_float2(v0, v1);
            *reinterpret_cast<float2*>(C + (size_t)(row + 8) * N + col) = make_float2(v2, v3);
        }
    }
}

__global__ void __launch_bounds__(256, 2) gemm_in_x(const float* __restrict__ x,
                                                    const float* __restrict__ bi) {
    gemm_tf32_body(x, g_wi, bi, g_qkv, 3 * E_, E_, 1, 1);
}
__global__ void __launch_bounds__(256, 2) gemm_out_k(const float* __restrict__ bo) {
    gemm_tf32_body(g_att, g_wo, bo, g_p1, E_, E_, 0, 1);
}
__global__ void __launch_bounds__(256, 2) gemm_c_k(const float* __restrict__ bc,
                                                   float* __restrict__ out) {
    gemm_tf32_body(g_p1, g_wc, bc, out, E_, E_, 0, 0);
}

// ---------------------------------------------------------------------------
// Tensor-core causal flash attention, cp.async pipelined.
// grid (T/64, B*H) qb-reversed, 128 threads (4 warps), warp = 16 query rows.
// KV tile 32, raw [key][d] smem layout (stride 68), double-buffered with
// depth-1 prefetch (same proven structure as the GEMM pipeline).
// Bank math: K-frag (68g+t)%32=4g+t distinct; V-frag (68t+g)%32=4t+g distinct.
// Q staged via cp.async into the K buffers once, then they are recycled.
// Static smem 2*(2*32*68)*4 = 34,816 B; 3 CTAs/SM.
// ---------------------------------------------------------------------------
#define KT_ 32
#define FS_ 68

__global__ void __launch_bounds__(128, 3) flash_attn()
{
    __shared__ __align__(16) float Ks[2][KT_][FS_];
    __shared__ __align__(16) float Vs[2][KT_][FS_];

    const float* qkv = g_qkv;
    const int tid  = threadIdx.x;
    const int lane = tid & 31;
    const int w    = tid >> 5;
    const int gid  = lane >> 2;
    const int tig  = lane & 3;
    const int qb   = gridDim.x - 1 - blockIdx.x;   // longest first
    const int b    = blockIdx.y >> 4;
    const int h    = blockIdx.y & 15;
    const size_t base = (size_t)b * T_ * 3 * E_ + (size_t)h * DH_;

    // ---- stage Q (64x64) into Ks[0..1] via cp.async ----
#pragma unroll
    for (int i = 0; i < 8; i++) {
        int idx = tid + i * 128;          // 0..1023
        int row = idx >> 4;               // 0..63
        int c4  = (idx & 15) << 2;        // 0..60
        cpa16(sptr(&Ks[row >> 5][row & 31][c4]),
              qkv + base + (size_t)(qb * 64 + row) * 3 * E_ + c4);
    }
    asm volatile("cp.async.commit_group;\n" ::: "memory");
    asm volatile("cp.async.wait_group 0;\n" ::: "memory");
    __syncthreads();

    // ---- Q fragments to registers (scale 1/8 folded: exact pow2) ----
    uint32_t qf[8][4];
    {
        const int r0 = w * 16 + gid;      // 0..55
        const int r1 = r0 + 8;            // 8..63
#pragma unroll
        for (int kc = 0; kc < 8; kc++) {
            qf[kc][0] = __float_as_uint(Ks[r0 >> 5][r0 & 31][kc * 8 + tig    ] * 0.125f);
            qf[kc][1] = __float_as_uint(Ks[r1 >> 5][r1 & 31][kc * 8 + tig    ] * 0.125f);
            qf[kc][2] = __float_as_uint(Ks[r0 >> 5][r0 & 31][kc * 8 + tig + 4] * 0.125f);
            qf[kc][3] = __float_as_uint(Ks[r1 >> 5][r1 & 31][kc * 8 + tig + 4] * 0.125f);
        }
    }
    __syncthreads();   // everyone done reading Q; buffers reusable

    auto issue_kv = [&](int kb, int s) {
#pragma unroll
        for (int i = 0; i < 4; i++) {
            int idx = tid + i * 128;      // 0..511
            int row = idx >> 4;           // 0..31
            int c4  = (idx & 15) << 2;
            size_t tok = base + (size_t)(kb * KT_ + row) * 3 * E_;
            cpa16(sptr(&Ks[s][row][c4]), qkv + tok + E_ + c4);
            cpa16(sptr(&Vs[s][row][c4]), qkv + tok + 2 * E_ + c4);
        }
    };

    issue_kv(0, 0);
    asm volatile("cp.async.commit_group;\n" ::: "memory");

    float m0 = -1e30f, m1 = -1e30f, l0 = 0.f, l1 = 0.f;
    float oacc[8][4];
#pragma unroll
    for (int n = 0; n < 8; n++)
#pragma unroll
        for (int r = 0; r < 4; r++) oacc[n][r] = 0.f;

    const int nkb = 2 * qb + 2;          // causal: KV tiles 0 .. 2qb+1
    for (int kb = 0; kb < nkb; kb++) {
        asm volatile("cp.async.wait_group 0;\n" ::: "memory");  // tile kb ready
        __syncthreads();            // + all warps done computing tile kb-1
        if (kb + 1 < nkb) {         // prefetch overlaps compute below
            issue_kv(kb + 1, (kb + 1) & 1);
            asm volatile("cp.async.commit_group;\n" ::: "memory");
        }
        const float (*Kb)[FS_] = Ks[kb & 1];
        const float (*Vb)[FS_] = Vs[kb & 1];

        // ---- S = Q K^T : 4 n-tiles (32 keys) x 8 k-steps (d=64) ----
        float sacc[4][4];
#pragma unroll
        for (int n = 0; n < 4; n++)
#pragma unroll
            for (int r = 0; r < 4; r++) sacc[n][r] = 0.f;

#pragma unroll
        for (int kc = 0; kc < 8; kc++)
#pragma unroll
            for (int n = 0; n < 4; n++) {
                float b0 = Kb[n * 8 + gid][kc * 8 + tig];
                float b1 = Kb[n * 8 + gid][kc * 8 + tig + 4];
                mma_tf32(sacc[n][0], sacc[n][1], sacc[n][2], sacc[n][3],
                         qf[kc][0], qf[kc][1], qf[kc][2], qf[kc][3],
                         __float_as_uint(b0), __float_as_uint(b1));
            }

        // ---- causal mask (tiles straddling the diagonal) ----
        if (kb >= 2 * qb) {
            const int rg0 = qb * 64 + w * 16 + gid;
#pragma unroll
            for (int n = 0; n < 4; n++) {
                int c = kb * KT_ + n * 8 + 2 * tig;
                if (c     > rg0    ) sacc[n][0] = -1e30f;
                if (c + 1 > rg0    ) sacc[n][1] = -1e30f;
                if (c     > rg0 + 8) sacc[n][2] = -1e30f;
                if (c + 1 > rg0 + 8) sacc[n][3] = -1e30f;
            }
        }

        // ---- online softmax (rows gid / gid+8), quad-lane reduce ----
        float mx0 = -1e30f, mx1 = -1e30f;
#pragma unroll
        for (int n = 0; n < 4; n++) {
            mx0 = fmaxf(mx0, fmaxf(sacc[n][0], sacc[n][1]));
            mx1 = fmaxf(mx1, fmaxf(sacc[n][2], sacc[n][3]));
        }
        mx0 = fmaxf(mx0, __shfl_xor_sync(0xffffffffu, mx0, 1));
        mx0 = fmaxf(mx0, __shfl_xor_sync(0xffffffffu, mx0, 2));
        mx1 = fmaxf(mx1, __shfl_xor_sync(0xffffffffu, mx1, 1));
        mx1 = fmaxf(mx1, __shfl_xor_sync(0xffffffffu, mx1, 2));
        float mn0 = fmaxf(m0, mx0), mn1 = fmaxf(m1, mx1);
        float al0 = __expf(m0 - mn0), al1 = __expf(m1 - mn1);
        m0 = mn0; m1 = mn1;

        float sum0 = 0.f, sum1 = 0.f;
#pragma unroll
        for (int n = 0; n < 4; n++) {
            float p0 = tf32r(__expf(sacc[n][0] - mn0));
            float p1 = tf32r(__expf(sacc[n][1] - mn0));
            float p2 = tf32r(__expf(sacc[n][2] - mn1));
            float p3 = tf32r(__expf(sacc[n][3] - mn1));
            sum0 += p0 + p1; sum1 += p2 + p3;
            sacc[n][0] = p0; sacc[n][1] = p1; sacc[n][2] = p2; sacc[n][3] = p3;
        }
        sum0 += __shfl_xor_sync(0xffffffffu, sum0, 1);
        sum0 += __shfl_xor_sync(0xffffffffu, sum0, 2);
        sum1 += __shfl_xor_sync(0xffffffffu, sum1, 1);
        sum1 += __shfl_xor_sync(0xffffffffu, sum1, 2);
        l0 = l0 * al0 + sum0;
        l1 = l1 * al1 + sum1;
#pragma unroll
        for (int n = 0; n < 8; n++) {
            oacc[n][0] *= al0; oacc[n][1] *= al0;
            oacc[n][2] *= al1; oacc[n][3] *= al1;
        }

        // ---- O += P V : shuffle P C-frags -> A-frags, 4 k-chunks ----
        const int src0 = (lane & 28) | (tig >> 1);
        const int src1 = src0 + 2;
        const bool odd = (tig & 1);
#pragma unroll
        for (int kc = 0; kc < 4; kc++) {
            float v00 = __shfl_sync(0xffffffffu, sacc[kc][0], src0);
            float v01 = __shfl_sync(0xffffffffu, sacc[kc][1], src0);
            float v10 = __shfl_sync(0xffffffffu, sacc[kc][0], src1);
            float v11 = __shfl_sync(0xffffffffu, sacc[kc][1], src1);
            float v20 = __shfl_sync(0xffffffffu, sacc[kc][2], src0);
            float v21 = __shfl_sync(0xffffffffu, sacc[kc][3], src0);
            float v30 = __shfl_sync(0xffffffffu, sacc[kc][2], src1);
            float v31 = __shfl_sync(0xffffffffu, sacc[kc][3], src1);
            uint32_t a0 = __float_as_uint(odd ? v01 : v00);
            uint32_t a2 = __float_as_uint(odd ? v11 : v10);
            uint32_t a1 = __float_as_uint(odd ? v21 : v20);
            uint32_t a3 = __float_as_uint(odd ? v31 : v30);
#pragma unroll
            for (int n = 0; n < 8; n++) {
                float b0 = Vb[kc * 8 + tig    ][n * 8 + gid];
                float b1 = Vb[kc * 8 + tig + 4][n * 8 + gid];
                mma_tf32(oacc[n][0], oacc[n][1], oacc[n][2], oacc[n][3],
                         a0, a1, a2, a3,
                         __float_as_uint(b0), __float_as_uint(b1));
            }
        }
    }

    // ---- epilogue: normalize, round to tf32 grid, write [B,T,E] ----
    const float inv0 = 1.f / l0, inv1 = 1.f / l1;
    const int row0 = qb * 64 + w * 16 + gid;
#pragma unroll
    for (int n = 0; n < 8; n++) {
        int col = h * DH_ + n * 8 + 2 * tig;
        size_t o0 = ((size_t)b * T_ + row0) * E_ + col;
        size_t o1 = ((size_t)b * T_ + row0 + 8) * E_ + col;
        *reinterpret_cast<float2*>(g_att + o0) =
            make_float2(tf32r(oacc[n][0] * inv0), tf32r(oacc[n][1] * inv0));
        *reinterpret_cast<float2*>(g_att + o1) =
            make_float2(tf32r(oacc[n][2] * inv1), tf32r(oacc[n][3] * inv1));
    }
}

// ---------------------------------------------------------------------------
extern "C" void kernel_launch(void* const* d_in, const int* in_sizes, int n_in,
                              void* d_out, int out_size)
{
    const float* x  = (const float*)d_in[0];
    const float* wi = (const float*)d_in[1];
    const float* bi = (const float*)d_in[2];
    const float* wo = (const float*)d_in[3];
    const float* bo = (const float*)d_in[4];
    const float* wc = (const float*)d_in[5];
    const float* bc = (const float*)d_in[6];
    float* out = (float*)d_out;

    const int M = B_ * T_;  // 8192

    cvt_w<<<(5 * E_ * E_ / 4 + 255) / 256, 256>>>(wi, wo, wc);
    gemm_in_x<<<dim3(3 * E_ / 128, M / 128), 256>>>(x, bi);
    flash_attn<<<dim3(T_ / 64, B_ * H_), 128>>>();
    gemm_out_k<<<dim3(E_ / 128, M / 128), 256>>>(bo);
    gemm_c_k<<<dim3(E_ / 128, M / 128), 256>>>(bc, out);
}

// round 11
// speedup vs baseline: 1.2097x; 1.1129x over previous
#include <cuda_runtime.h>
#include <math.h>
#include <stdint.h>

#define B_  8
#define T_  1024
#define E_  1024
#define H_  16
#define DH_ 64

// Scratch (__device__ globals: allocation-free rule; zero-initialized)
__device__ float g_qkv  [(size_t)B_ * T_ * 3 * E_];  // 96 MB
__device__ float g_att  [(size_t)B_ * T_ * E_];      // 32 MB
__device__ float g_wi   [(size_t)3 * E_ * E_];       // rounded weights
__device__ float g_wo   [(size_t)E_ * E_];
__device__ float g_wc   [(size_t)E_ * E_];
__device__ float g_woT  [(size_t)E_ * E_];           // Wo^T (rounded)
__device__ float g_wcomb[(size_t)E_ * E_];           // Wc@Wo (rounded)
__device__ float g_bcomb[E_];                        // Wc*bo + bc
__device__ float g_bzero[E_];                        // stays zero (never written)

// ---------------------------------------------------------------------------
__device__ __forceinline__ float tf32r(float x) {
    uint32_t u;
    asm("cvt.rna.tf32.f32 %0, %1;" : "=r"(u) : "f"(x));
    return __uint_as_float(u);
}
__device__ __forceinline__ uint32_t sptr(const void* p) {
    return (uint32_t)__cvta_generic_to_shared(p);
}
__device__ __forceinline__ void cpa16(uint32_t dst, const float* src) {
    asm volatile("cp.async.cg.shared.global [%0], [%1], 16;\n" :: "r"(dst), "l"(src));
}
__device__ __forceinline__ void mma_tf32(
    float& c0, float& c1, float& c2, float& c3,
    uint32_t a0, uint32_t a1, uint32_t a2, uint32_t a3,
    uint32_t b0, uint32_t b1)
{
    asm volatile(
        "mma.sync.aligned.m16n8k8.row.col.f32.tf32.tf32.f32 "
        "{%0,%1,%2,%3},{%4,%5,%6,%7},{%8,%9},{%0,%1,%2,%3};"
        : "+f"(c0), "+f"(c1), "+f"(c2), "+f"(c3)
        : "r"(a0), "r"(a1), "r"(a2), "r"(a3), "r"(b0), "r"(b1));
}

// round weights to tf32 grid (rna, unbiased) ---------------------------------
__global__ void __launch_bounds__(256) cvt_w(const float* __restrict__ wi,
                                             const float* __restrict__ wo,
                                             const float* __restrict__ wc) {
    int i = blockIdx.x * blockDim.x + threadIdx.x;
    const int n_i = 3 * E_ * E_ / 4;
    const int n_o = E_ * E_ / 4;
    const float4* src;
    float4* dst;
    int j;
    if (i < n_i)                 { src = (const float4*)wi; dst = (float4*)g_wi; j = i; }
    else if (i < n_i + n_o)      { src = (const float4*)wo; dst = (float4*)g_wo; j = i - n_i; }
    else if (i < n_i + 2 * n_o)  { src = (const float4*)wc; dst = (float4*)g_wc; j = i - n_i - n_o; }
    else return;
    float4 v = src[j];
    v.x = tf32r(v.x); v.y = tf32r(v.y); v.z = tf32r(v.z); v.w = tf32r(v.w);
    dst[j] = v;
}

// 1024x1024 transpose: g_woT = g_wo^T ----------------------------------------
__global__ void __launch_bounds__(256) transpose_wo() {
    __shared__ float t[32][33];
    int x = blockIdx.x * 32 + threadIdx.x;
    int y = blockIdx.y * 32 + threadIdx.y;
#pragma unroll
    for (int i = 0; i < 32; i += 8)
        t[threadIdx.y + i][threadIdx.x] = g_wo[(size_t)(y + i) * E_ + x];
    __syncthreads();
    x = blockIdx.y * 32 + threadIdx.x;
    y = blockIdx.x * 32 + threadIdx.y;
#pragma unroll
    for (int i = 0; i < 32; i += 8)
        g_woT[(size_t)(y + i) * E_ + x] = t[threadIdx.x][threadIdx.y + i];
}

// b_comb = Wc * bo + bc (fp32, warp per row) ---------------------------------
__global__ void __launch_bounds__(256) bcomb_k(const float* __restrict__ wc,
                                               const float* __restrict__ bo,
                                               const float* __restrict__ bc) {
    int row  = blockIdx.x * 8 + (threadIdx.x >> 5);
    int lane = threadIdx.x & 31;
    const float* wr = wc + (size_t)row * E_;
    float s = 0.f;
    for (int j = lane; j < E_; j += 32) s += wr[j] * bo[j];
#pragma unroll
    for (int o = 16; o; o >>= 1) s += __shfl_xor_sync(0xffffffffu, s, o);
    if (lane == 0) g_bcomb[row] = bc[row] + s;
}

// ---------------------------------------------------------------------------
// TF32 tensor-core GEMM (R8/R9, passing): 128x128 tile, BK=16, 8 warps 2x4,
// 2-stage cp.async, one __syncthreads per K-step. Static smem 40 KB.
// ---------------------------------------------------------------------------
__device__ __forceinline__ void gemm_tf32_body(
    const float* __restrict__ A, const float* __restrict__ Bm,
    const float* __restrict__ bias, float* __restrict__ C,
    int N, int K, int round_a, int round_out)
{
    __shared__ float As[2][128][20];
    __shared__ float Bs[2][128][20];

    const int tid  = threadIdx.x;
    const int lane = tid & 31;
    const int wid  = tid >> 5;
    const int gid  = lane >> 2;
    const int tig  = lane & 3;
    const int wm   = (wid >> 2) * 64;
    const int wn   = (wid & 3) * 32;
    const int bm   = blockIdx.y * 128;
    const int bn   = blockIdx.x * 128;

    float acc[4][4][4];
#pragma unroll
    for (int mt = 0; mt < 4; mt++)
#pragma unroll
        for (int nt = 0; nt < 4; nt++)
#pragma unroll
            for (int r = 0; r < 4; r++) acc[mt][nt][r] = 0.f;

    auto issue = [&](int k0, int s) {
#pragma unroll
        for (int i = 0; i < 2; i++) {
            int idx = tid + i * 256;
            int row = idx >> 2;
            int c4  = (idx & 3) << 2;
            cpa16(sptr(&As[s][row][c4]), A  + (size_t)(bm + row) * K + k0 + c4);
            cpa16(sptr(&Bs[s][row][c4]), Bm + (size_t)(bn + row) * K + k0 + c4);
        }
    };

    issue(0, 0);
    asm volatile("cp.async.commit_group;\n" ::: "memory");

    const int NIT = K / 16;
    for (int it = 0; it < NIT; it++) {
        asm volatile("cp.async.wait_group 0;\n" ::: "memory");
        __syncthreads();
        if (it + 1 < NIT) {
            issue((it + 1) * 16, (it + 1) & 1);
            asm volatile("cp.async.commit_group;\n" ::: "memory");
        }

        const int s = it & 1;
#pragma unroll
        for (int ks = 0; ks < 2; ks++) {
            const int kk = ks * 8 + tig;
            uint32_t a[4][4], b[4][2];
#pragma unroll
            for (int mt = 0; mt < 4; mt++) {
                int r0 = wm + mt * 16 + gid;
                float a0 = As[s][r0    ][kk    ];
                float a1 = As[s][r0 + 8][kk    ];
                float a2 = As[s][r0    ][kk + 4];
                float a3 = As[s][r0 + 8][kk + 4];
                if (round_a) { a0 = tf32r(a0); a1 = tf32r(a1); a2 = tf32r(a2); a3 = tf32r(a3); }
                a[mt][0] = __float_as_uint(a0);
                a[mt][1] = __float_as_uint(a1);
                a[mt][2] = __float_as_uint(a2);
                a[mt][3] = __float_as_uint(a3);
            }
#pragma unroll
            for (int nt = 0; nt < 4; nt++) {
                int c0i = wn + nt * 8 + gid;
                b[nt][0] = __float_as_uint(Bs[s][c0i][kk    ]);
                b[nt][1] = __float_as_uint(Bs[s][c0i][kk + 4]);
            }
#pragma unroll
            for (int mt = 0; mt < 4; mt++)
#pragma unroll
                for (int nt = 0; nt < 4; nt++)
                    mma_tf32(acc[mt][nt][0], acc[mt][nt][1], acc[mt][nt][2], acc[mt][nt][3],
                             a[mt][0], a[mt][1], a[mt][2], a[mt][3], b[nt][0], b[nt][1]);
        }
    }

#pragma unroll
    for (int mt = 0; mt < 4; mt++) {
#pragma unroll
        for (int nt = 0; nt < 4; nt++) {
            int row = bm + wm + mt * 16 + gid;
            int col = bn + wn + nt * 8 + tig * 2;
            float bv0 = bias[col], bv1 = bias[col + 1];
            float v0 = acc[mt][nt][0] + bv0;
            float v1 = acc[mt][nt][1] + bv1;
            float v2 = acc[mt][nt][2] + bv0;
            float v3 = acc[mt][nt][3] + bv1;
            if (round_out) {
                v0 = tf32r(v0); v1 = tf32r(v1); v2 = tf32r(v2); v3 = tf32r(v3);
            }
            *reinterpret_cast<float2*>(C + (size_t)row * N + col) = make_float2(v0, v1);
            *reinterpret_cast<float2*>(C + (size_t)(row + 8) * N + col) = make_float2(v2, v3);
        }
    }
}

__global__ void __launch_bounds__(256, 2) gemm_in_x(const float* __restrict__ x,
                                                    const float* __restrict__ bi) {
    gemm_tf32_body(x, g_wi, bi, g_qkv, 3 * E_, E_, 1, 1);   // round A in-register
}
// W_comb = Wc @ Wo  (A = g_wc rounded, B = g_woT rounded), output rounded
__global__ void __launch_bounds__(256, 2) gemm_wcomb() {
    gemm_tf32_body(g_wc, g_woT, g_bzero, g_wcomb, E_, E_, 0, 1);
}
// out = att @ W_comb^T + b_comb  (single fused projection)
__global__ void __launch_bounds__(256, 2) gemm_fin(float* __restrict__ out) {
    gemm_tf32_body(g_att, g_wcomb, g_bcomb, out, E_, E_, 0, 0);
}

// ---------------------------------------------------------------------------
// Tensor-core causal flash attention, cp.async pipelined (R9, passing).
// ---------------------------------------------------------------------------
#define KT_ 32
#define FS_ 68

__global__ void __launch_bounds__(128, 3) flash_attn()
{
    __shared__ __align__(16) float Ks[2][KT_][FS_];
    __shared__ __align__(16) float Vs[2][KT_][FS_];

    const float* qkv = g_qkv;
    const int tid  = threadIdx.x;
    const int lane = tid & 31;
    const int w    = tid >> 5;
    const int gid  = lane >> 2;
    const int tig  = lane & 3;
    const int qb   = gridDim.x - 1 - blockIdx.x;
    const int b    = blockIdx.y >> 4;
    const int h    = blockIdx.y & 15;
    const size_t base = (size_t)b * T_ * 3 * E_ + (size_t)h * DH_;

#pragma unroll
    for (int i = 0; i < 8; i++) {
        int idx = tid + i * 128;
        int row = idx >> 4;
        int c4  = (idx & 15) << 2;
        cpa16(sptr(&Ks[row >> 5][row & 31][c4]),
              qkv + base + (size_t)(qb * 64 + row) * 3 * E_ + c4);
    }
    asm volatile("cp.async.commit_group;\n" ::: "memory");
    asm volatile("cp.async.wait_group 0;\n" ::: "memory");
    __syncthreads();

    uint32_t qf[8][4];
    {
        const int r0 = w * 16 + gid;
        const int r1 = r0 + 8;
#pragma unroll
        for (int kc = 0; kc < 8; kc++) {
            qf[kc][0] = __float_as_uint(Ks[r0 >> 5][r0 & 31][kc * 8 + tig    ] * 0.125f);
            qf[kc][1] = __float_as_uint(Ks[r1 >> 5][r1 & 31][kc * 8 + tig    ] * 0.125f);
            qf[kc][2] = __float_as_uint(Ks[r0 >> 5][r0 & 31][kc * 8 + tig + 4] * 0.125f);
            qf[kc][3] = __float_as_uint(Ks[r1 >> 5][r1 & 31][kc * 8 + tig + 4] * 0.125f);
        }
    }
    __syncthreads();

    auto issue_kv = [&](int kb, int s) {
#pragma unroll
        for (int i = 0; i < 4; i++) {
            int idx = tid + i * 128;
            int row = idx >> 4;
            int c4  = (idx & 15) << 2;
            size_t tok = base + (size_t)(kb * KT_ + row) * 3 * E_;
            cpa16(sptr(&Ks[s][row][c4]), qkv + tok + E_ + c4);
            cpa16(sptr(&Vs[s][row][c4]), qkv + tok + 2 * E_ + c4);
        }
    };

    issue_kv(0, 0);
    asm volatile("cp.async.commit_group;\n" ::: "memory");

    float m0 = -1e30f, m1 = -1e30f, l0 = 0.f, l1 = 0.f;
    float oacc[8][4];
#pragma unroll
    for (int n = 0; n < 8; n++)
#pragma unroll
        for (int r = 0; r < 4; r++) oacc[n][r] = 0.f;

    const int nkb = 2 * qb + 2;
    for (int kb = 0; kb < nkb; kb++) {
        asm volatile("cp.async.wait_group 0;\n" ::: "memory");
        __syncthreads();
        if (kb + 1 < nkb) {
            issue_kv(kb + 1, (kb + 1) & 1);
            asm volatile("cp.async.commit_group;\n" ::: "memory");
        }
        const float (*Kb)[FS_] = Ks[kb & 1];
        const float (*Vb)[FS_] = Vs[kb & 1];

        float sacc[4][4];
#pragma unroll
        for (int n = 0; n < 4; n++)
#pragma unroll
            for (int r = 0; r < 4; r++) sacc[n][r] = 0.f;

#pragma unroll
        for (int kc = 0; kc < 8; kc++)
#pragma unroll
            for (int n = 0; n < 4; n++) {
                float b0 = Kb[n * 8 + gid][kc * 8 + tig];
                float b1 = Kb[n * 8 + gid][kc * 8 + tig + 4];
                mma_tf32(sacc[n][0], sacc[n][1], sacc[n][2], sacc[n][3],
                         qf[kc][0], qf[kc][1], qf[kc][2], qf[kc][3],
                         __float_as_uint(b0), __float_as_uint(b1));
            }

        if (kb >= 2 * qb) {
            const int rg0 = qb * 64 + w * 16 + gid;
#pragma unroll
            for (int n = 0; n < 4; n++) {
                int c = kb * KT_ + n * 8 + 2 * tig;
                if (c     > rg0    ) sacc[n][0] = -1e30f;
                if (c + 1 > rg0    ) sacc[n][1] = -1e30f;
                if (c     > rg0 + 8) sacc[n][2] = -1e30f;
                if (c + 1 > rg0 + 8) sacc[n][3] = -1e30f;
            }
        }

        float mx0 = -1e30f, mx1 = -1e30f;
#pragma unroll
        for (int n = 0; n < 4; n++) {
            mx0 = fmaxf(mx0, fmaxf(sacc[n][0], sacc[n][1]));
            mx1 = fmaxf(mx1, fmaxf(sacc[n][2], sacc[n][3]));
        }
        mx0 = fmaxf(mx0, __shfl_xor_sync(0xffffffffu, mx0, 1));
        mx0 = fmaxf(mx0, __shfl_xor_sync(0xffffffffu, mx0, 2));
        mx1 = fmaxf(mx1, __shfl_xor_sync(0xffffffffu, mx1, 1));
        mx1 = fmaxf(mx1, __shfl_xor_sync(0xffffffffu, mx1, 2));
        float mn0 = fmaxf(m0, mx0), mn1 = fmaxf(m1, mx1);
        float al0 = __expf(m0 - mn0), al1 = __expf(m1 - mn1);
        m0 = mn0; m1 = mn1;

        float sum0 = 0.f, sum1 = 0.f;
#pragma unroll
        for (int n = 0; n < 4; n++) {
            float p0 = tf32r(__expf(sacc[n][0] - mn0));
            float p1 = tf32r(__expf(sacc[n][1] - mn0));
            float p2 = tf32r(__expf(sacc[n][2] - mn1));
            float p3 = tf32r(__expf(sacc[n][3] - mn1));
            sum0 += p0 + p1; sum1 += p2 + p3;
            sacc[n][0] = p0; sacc[n][1] = p1; sacc[n][2] = p2; sacc[n][3] = p3;
        }
        sum0 += __shfl_xor_sync(0xffffffffu, sum0, 1);
        sum0 += __shfl_xor_sync(0xffffffffu, sum0, 2);
        sum1 += __shfl_xor_sync(0xffffffffu, sum1, 1);
        sum1 += __shfl_xor_sync(0xffffffffu, sum1, 2);
        l0 = l0 * al0 + sum0;
        l1 = l1 * al1 + sum1;
#pragma unroll
        for (int n = 0; n < 8; n++) {
            oacc[n][0] *= al0; oacc[n][1] *= al0;
            oacc[n][2] *= al1; oacc[n][3] *= al1;
        }

        const int src0 = (lane & 28) | (tig >> 1);
        const int src1 = src0 + 2;
        const bool odd = (tig & 1);
#pragma unroll
        for (int kc = 0; kc < 4; kc++) {
            float v00 = __shfl_sync(0xffffffffu, sacc[kc][0], src0);
            float v01 = __shfl_sync(0xffffffffu, sacc[kc][1], src0);
            float v10 = __shfl_sync(0xffffffffu, sacc[kc][0], src1);
            float v11 = __shfl_sync(0xffffffffu, sacc[kc][1], src1);
            float v20 = __shfl_sync(0xffffffffu, sacc[kc][2], src0);
            float v21 = __shfl_sync(0xffffffffu, sacc[kc][3], src0);
            float v30 = __shfl_sync(0xffffffffu, sacc[kc][2], src1);
            float v31 = __shfl_sync(0xffffffffu, sacc[kc][3], src1);
            uint32_t a0 = __float_as_uint(odd ? v01 : v00);
            uint32_t a2 = __float_as_uint(odd ? v11 : v10);
            uint32_t a1 = __float_as_uint(odd ? v21 : v20);
            uint32_t a3 = __float_as_uint(odd ? v31 : v30);
#pragma unroll
            for (int n = 0; n < 8; n++) {
                float b0 = Vb[kc * 8 + tig    ][n * 8 + gid];
                float b1 = Vb[kc * 8 + tig + 4][n * 8 + gid];
                mma_tf32(oacc[n][0], oacc[n][1], oacc[n][2], oacc[n][3],
                         a0, a1, a2, a3,
                         __float_as_uint(b0), __float_as_uint(b1));
            }
        }
    }

    const float inv0 = 1.f / l0, inv1 = 1.f / l1;
    const int row0 = qb * 64 + w * 16 + gid;
#pragma unroll
    for (int n = 0; n < 8; n++) {
        int col = h * DH_ + n * 8 + 2 * tig;
        size_t o0 = ((size_t)b * T_ + row0) * E_ + col;
        size_t o1 = ((size_t)b * T_ + row0 + 8) * E_ + col;
        *reinterpret_cast<float2*>(g_att + o0) =
            make_float2(tf32r(oacc[n][0] * inv0), tf32r(oacc[n][1] * inv0));
        *reinterpret_cast<float2*>(g_att + o1) =
            make_float2(tf32r(oacc[n][2] * inv1), tf32r(oacc[n][3] * inv1));
    }
}

// ---------------------------------------------------------------------------
extern "C" void kernel_launch(void* const* d_in, const int* in_sizes, int n_in,
                              void* d_out, int out_size)
{
    const float* x  = (const float*)d_in[0];
    const float* wi = (const float*)d_in[1];
    const float* bi = (const float*)d_in[2];
    const float* wo = (const float*)d_in[3];
    const float* bo = (const float*)d_in[4];
    const float* wc = (const float*)d_in[5];
    const float* bc = (const float*)d_in[6];
    float* out = (float*)d_out;

    const int M = B_ * T_;  // 8192

    // weight prep
    cvt_w<<<(5 * E_ * E_ / 4 + 255) / 256, 256>>>(wi, wo, wc);
    transpose_wo<<<dim3(32, 32), dim3(32, 8)>>>();
    gemm_wcomb<<<dim3(E_ / 128, E_ / 128), 256>>>();
    bcomb_k<<<E_ / 8, 256>>>(wc, bo, bc);

    // main chain: QKV proj -> attention -> fused (out_proj @ c_proj)
    gemm_in_x<<<dim3(3 * E_ / 128, M / 128), 256>>>(x, bi);
    flash_attn<<<dim3(T_ / 64, B_ * H_), 128>>>();
    gemm_fin<<<dim3(E_ / 128, M / 128), 256>>>(out);
}

// round 12
// speedup vs baseline: 1.3413x; 1.1088x over previous
#include <cuda_runtime.h>
#include <math.h>
#include <stdint.h>

#define B_  8
#define T_  1024
#define E_  1024
#define H_  16
#define DH_ 64

// Scratch (__device__ globals: allocation-free rule; zero-initialized)
__device__ float g_qkv  [(size_t)B_ * T_ * 3 * E_];  // 96 MB
__device__ float g_att  [(size_t)B_ * T_ * E_];      // 32 MB
__device__ float g_wi   [(size_t)3 * E_ * E_];       // rounded weights
__device__ float g_wo   [(size_t)E_ * E_];
__device__ float g_wc   [(size_t)E_ * E_];
__device__ float g_woT  [(size_t)E_ * E_];           // Wo^T (rounded)
__device__ float g_wcomb[(size_t)E_ * E_];           // Wc@Wo (rounded)
__device__ float g_bcomb[E_];                        // Wc*bo + bc
__device__ float g_bzero[E_];                        // stays zero (never written)

// ---------------------------------------------------------------------------
__device__ __forceinline__ float tf32r(float x) {
    uint32_t u;
    asm("cvt.rna.tf32.f32 %0, %1;" : "=r"(u) : "f"(x));
    return __uint_as_float(u);
}
__device__ __forceinline__ uint32_t sptr(const void* p) {
    return (uint32_t)__cvta_generic_to_shared(p);
}
__device__ __forceinline__ void cpa16(uint32_t dst, const float* src) {
    asm volatile("cp.async.cg.shared.global [%0], [%1], 16;\n" :: "r"(dst), "l"(src));
}
__device__ __forceinline__ void mma_tf32(
    float& c0, float& c1, float& c2, float& c3,
    uint32_t a0, uint32_t a1, uint32_t a2, uint32_t a3,
    uint32_t b0, uint32_t b1)
{
    asm volatile(
        "mma.sync.aligned.m16n8k8.row.col.f32.tf32.tf32.f32 "
        "{%0,%1,%2,%3},{%4,%5,%6,%7},{%8,%9},{%0,%1,%2,%3};"
        : "+f"(c0), "+f"(c1), "+f"(c2), "+f"(c3)
        : "r"(a0), "r"(a1), "r"(a2), "r"(a3), "r"(b0), "r"(b1));
}

// round weights to tf32 grid (rna, unbiased) ---------------------------------
__global__ void __launch_bounds__(256) cvt_w(const float* __restrict__ wi,
                                             const float* __restrict__ wo,
                                             const float* __restrict__ wc) {
    int i = blockIdx.x * blockDim.x + threadIdx.x;
    const int n_i = 3 * E_ * E_ / 4;
    const int n_o = E_ * E_ / 4;
    const float4* src;
    float4* dst;
    int j;
    if (i < n_i)                 { src = (const float4*)wi; dst = (float4*)g_wi; j = i; }
    else if (i < n_i + n_o)      { src = (const float4*)wo; dst = (float4*)g_wo; j = i - n_i; }
    else if (i < n_i + 2 * n_o)  { src = (const float4*)wc; dst = (float4*)g_wc; j = i - n_i - n_o; }
    else return;
    float4 v = src[j];
    v.x = tf32r(v.x); v.y = tf32r(v.y); v.z = tf32r(v.z); v.w = tf32r(v.w);
    dst[j] = v;
}

// 1024x1024 transpose: g_woT = g_wo^T ----------------------------------------
__global__ void __launch_bounds__(256) transpose_wo() {
    __shared__ float t[32][33];
    int x = blockIdx.x * 32 + threadIdx.x;
    int y = blockIdx.y * 32 + threadIdx.y;
#pragma unroll
    for (int i = 0; i < 32; i += 8)
        t[threadIdx.y + i][threadIdx.x] = g_wo[(size_t)(y + i) * E_ + x];
    __syncthreads();
    x = blockIdx.y * 32 + threadIdx.x;
    y = blockIdx.x * 32 + threadIdx.y;
#pragma unroll
    for (int i = 0; i < 32; i += 8)
        g_woT[(size_t)(y + i) * E_ + x] = t[threadIdx.x][threadIdx.y + i];
}

// b_comb = Wc * bo + bc (fp32, warp per row) ---------------------------------
__global__ void __launch_bounds__(256) bcomb_k(const float* __restrict__ wc,
                                               const float* __restrict__ bo,
                                               const float* __restrict__ bc) {
    int row  = blockIdx.x * 8 + (threadIdx.x >> 5);
    int lane = threadIdx.x & 31;
    const float* wr = wc + (size_t)row * E_;
    float s = 0.f;
    for (int j = lane; j < E_; j += 32) s += wr[j] * bo[j];
#pragma unroll
    for (int o = 16; o; o >>= 1) s += __shfl_xor_sync(0xffffffffu, s, o);
    if (lane == 0) g_bcomb[row] = bc[row] + s;
}

// ---------------------------------------------------------------------------
// Small TF32 GEMM (R8/R9, passing): 128x128 tile — kept for the 64-CTA
// W_comb prep GEMM only.
// ---------------------------------------------------------------------------
__device__ __forceinline__ void gemm_tf32_body(
    const float* __restrict__ A, const float* __restrict__ Bm,
    const float* __restrict__ bias, float* __restrict__ C,
    int N, int K, int round_a, int round_out)
{
    __shared__ float As[2][128][20];
    __shared__ float Bs[2][128][20];

    const int tid  = threadIdx.x;
    const int lane = tid & 31;
    const int wid  = tid >> 5;
    const int gid  = lane >> 2;
    const int tig  = lane & 3;
    const int wm   = (wid >> 2) * 64;
    const int wn   = (wid & 3) * 32;
    const int bm   = blockIdx.y * 128;
    const int bn   = blockIdx.x * 128;

    float acc[4][4][4];
#pragma unroll
    for (int mt = 0; mt < 4; mt++)
#pragma unroll
        for (int nt = 0; nt < 4; nt++)
#pragma unroll
            for (int r = 0; r < 4; r++) acc[mt][nt][r] = 0.f;

    auto issue = [&](int k0, int s) {
#pragma unroll
        for (int i = 0; i < 2; i++) {
            int idx = tid + i * 256;
            int row = idx >> 2;
            int c4  = (idx & 3) << 2;
            cpa16(sptr(&As[s][row][c4]), A  + (size_t)(bm + row) * K + k0 + c4);
            cpa16(sptr(&Bs[s][row][c4]), Bm + (size_t)(bn + row) * K + k0 + c4);
        }
    };

    issue(0, 0);
    asm volatile("cp.async.commit_group;\n" ::: "memory");

    const int NIT = K / 16;
    for (int it = 0; it < NIT; it++) {
        asm volatile("cp.async.wait_group 0;\n" ::: "memory");
        __syncthreads();
        if (it + 1 < NIT) {
            issue((it + 1) * 16, (it + 1) & 1);
            asm volatile("cp.async.commit_group;\n" ::: "memory");
        }

        const int s = it & 1;
#pragma unroll
        for (int ks = 0; ks < 2; ks++) {
            const int kk = ks * 8 + tig;
            uint32_t a[4][4], b[4][2];
#pragma unroll
            for (int mt = 0; mt < 4; mt++) {
                int r0 = wm + mt * 16 + gid;
                float a0 = As[s][r0    ][kk    ];
                float a1 = As[s][r0 + 8][kk    ];
                float a2 = As[s][r0    ][kk + 4];
                float a3 = As[s][r0 + 8][kk + 4];
                if (round_a) { a0 = tf32r(a0); a1 = tf32r(a1); a2 = tf32r(a2); a3 = tf32r(a3); }
                a[mt][0] = __float_as_uint(a0);
                a[mt][1] = __float_as_uint(a1);
                a[mt][2] = __float_as_uint(a2);
                a[mt][3] = __float_as_uint(a3);
            }
#pragma unroll
            for (int nt = 0; nt < 4; nt++) {
                int c0i = wn + nt * 8 + gid;
                b[nt][0] = __float_as_uint(Bs[s][c0i][kk    ]);
                b[nt][1] = __float_as_uint(Bs[s][c0i][kk + 4]);
            }
#pragma unroll
            for (int mt = 0; mt < 4; mt++)
#pragma unroll
                for (int nt = 0; nt < 4; nt++)
                    mma_tf32(acc[mt][nt][0], acc[mt][nt][1], acc[mt][nt][2], acc[mt][nt][3],
                             a[mt][0], a[mt][1], a[mt][2], a[mt][3], b[nt][0], b[nt][1]);
        }
    }

#pragma unroll
    for (int mt = 0; mt < 4; mt++) {
#pragma unroll
        for (int nt = 0; nt < 4; nt++) {
            int row = bm + wm + mt * 16 + gid;
            int col = bn + wn + nt * 8 + tig * 2;
            float bv0 = bias[col], bv1 = bias[col + 1];
            float v0 = acc[mt][nt][0] + bv0;
            float v1 = acc[mt][nt][1] + bv1;
            float v2 = acc[mt][nt][2] + bv0;
            float v3 = acc[mt][nt][3] + bv1;
            if (round_out) {
                v0 = tf32r(v0); v1 = tf32r(v1); v2 = tf32r(v2); v3 = tf32r(v3);
            }
            *reinterpret_cast<float2*>(C + (size_t)row * N + col) = make_float2(v0, v1);
            *reinterpret_cast<float2*>(C + (size_t)(row + 8) * N + col) = make_float2(v2, v3);
        }
    }
}

// W_comb = Wc @ Wo  (A = g_wc rounded, B = g_woT rounded), output rounded
__global__ void __launch_bounds__(256, 2) gemm_wcomb() {
    gemm_tf32_body(g_wc, g_woT, g_bzero, g_wcomb, E_, E_, 0, 1);
}

// ---------------------------------------------------------------------------
// Big TF32 GEMM: 256x128 CTA tile, 8 warps 4(M)x2(N) of 64x64 warp tiles.
// BK=16, XOR-swizzled smem (stride 16 floats, c ^ ((row>>1&3)<<2)), exactly
// 48 KB static, 2-stage cp.async, one __syncthreads per K-step.
// Per-iter smem reads 24 KB (512 cyc) < HMMA 640 cyc -> tensor-bound.
// ---------------------------------------------------------------------------
#define SWZ(r) ((((r) >> 1) & 3) << 2)

__device__ __forceinline__ void gemm_tf32_big(
    const float* __restrict__ A, const float* __restrict__ Bm,
    const float* __restrict__ bias, float* __restrict__ C,
    int N, int K, int round_a, int round_out)
{
    __shared__ float As[2][256][16];
    __shared__ float Bs[2][128][16];

    const int tid  = threadIdx.x;
    const int lane = tid & 31;
    const int wid  = tid >> 5;
    const int gid  = lane >> 2;
    const int tig  = lane & 3;
    const int wm   = (wid >> 1) * 64;    // 0,64,128,192
    const int wn   = (wid & 1) * 64;     // 0,64
    const int bm   = blockIdx.y * 256;
    const int bn   = blockIdx.x * 128;

    float acc[4][8][4];
#pragma unroll
    for (int mt = 0; mt < 4; mt++)
#pragma unroll
        for (int nt = 0; nt < 8; nt++)
#pragma unroll
            for (int r = 0; r < 4; r++) acc[mt][nt][r] = 0.f;

    auto issue = [&](int k0, int s) {
#pragma unroll
        for (int i = 0; i < 4; i++) {            // A: 256 rows x 16 cols
            int idx = tid + i * 256;             // 0..1023
            int row = idx >> 2;                  // 0..255
            int c4  = (idx & 3) << 2;            // 0,4,8,12
            cpa16(sptr(&As[s][row][c4 ^ SWZ(row)]),
                  A + (size_t)(bm + row) * K + k0 + c4);
        }
#pragma unroll
        for (int i = 0; i < 2; i++) {            // B: 128 rows x 16 cols
            int idx = tid + i * 256;             // 0..511
            int row = idx >> 2;                  // 0..127
            int c4  = (idx & 3) << 2;
            cpa16(sptr(&Bs[s][row][c4 ^ SWZ(row)]),
                  Bm + (size_t)(bn + row) * K + k0 + c4);
        }
    };

    issue(0, 0);
    asm volatile("cp.async.commit_group;\n" ::: "memory");

    const int NIT = K / 16;
    for (int it = 0; it < NIT; it++) {
        asm volatile("cp.async.wait_group 0;\n" ::: "memory");
        __syncthreads();
        if (it + 1 < NIT) {
            issue((it + 1) * 16, (it + 1) & 1);
            asm volatile("cp.async.commit_group;\n" ::: "memory");
        }

        const int s = it & 1;
#pragma unroll
        for (int ks = 0; ks < 2; ks++) {
            const int kk = ks * 8 + tig;
            uint32_t a[4][4], b[8][2];
#pragma unroll
            for (int mt = 0; mt < 4; mt++) {
                int r0 = wm + mt * 16 + gid;
                int r1 = r0 + 8;
                float a0 = As[s][r0][ kk      ^ SWZ(r0)];
                float a1 = As[s][r1][ kk      ^ SWZ(r1)];
                float a2 = As[s][r0][(kk + 4) ^ SWZ(r0)];
                float a3 = As[s][r1][(kk + 4) ^ SWZ(r1)];
                if (round_a) { a0 = tf32r(a0); a1 = tf32r(a1); a2 = tf32r(a2); a3 = tf32r(a3); }
                a[mt][0] = __float_as_uint(a0);
                a[mt][1] = __float_as_uint(a1);
                a[mt][2] = __float_as_uint(a2);
                a[mt][3] = __float_as_uint(a3);
            }
#pragma unroll
            for (int nt = 0; nt < 8; nt++) {
                int c0i = wn + nt * 8 + gid;
                b[nt][0] = __float_as_uint(Bs[s][c0i][ kk      ^ SWZ(c0i)]);
                b[nt][1] = __float_as_uint(Bs[s][c0i][(kk + 4) ^ SWZ(c0i)]);
            }
#pragma unroll
            for (int mt = 0; mt < 4; mt++)
#pragma unroll
                for (int nt = 0; nt < 8; nt++)
                    mma_tf32(acc[mt][nt][0], acc[mt][nt][1], acc[mt][nt][2], acc[mt][nt][3],
                             a[mt][0], a[mt][1], a[mt][2], a[mt][3], b[nt][0], b[nt][1]);
        }
    }

#pragma unroll
    for (int mt = 0; mt < 4; mt++) {
#pragma unroll
        for (int nt = 0; nt < 8; nt++) {
            int row = bm + wm + mt * 16 + gid;
            int col = bn + wn + nt * 8 + tig * 2;
            float bv0 = bias[col], bv1 = bias[col + 1];
            float v0 = acc[mt][nt][0] + bv0;
            float v1 = acc[mt][nt][1] + bv1;
            float v2 = acc[mt][nt][2] + bv0;
            float v3 = acc[mt][nt][3] + bv1;
            if (round_out) {
                v0 = tf32r(v0); v1 = tf32r(v1); v2 = tf32r(v2); v3 = tf32r(v3);
            }
            *reinterpret_cast<float2*>(C + (size_t)row * N + col) = make_float2(v0, v1);
            *reinterpret_cast<float2*>(C + (size_t)(row + 8) * N + col) = make_float2(v2, v3);
        }
    }
}

__global__ void __launch_bounds__(256, 1) gemm_in_x(const float* __restrict__ x,
                                                    const float* __restrict__ bi) {
    gemm_tf32_big(x, g_wi, bi, g_qkv, 3 * E_, E_, 1, 1);   // round A in-register
}
// out = att @ W_comb^T + b_comb  (single fused projection)
__global__ void __launch_bounds__(256, 1) gemm_fin(float* __restrict__ out) {
    gemm_tf32_big(g_att, g_wcomb, g_bcomb, out, E_, E_, 0, 0);
}

// ---------------------------------------------------------------------------
// Tensor-core causal flash attention, cp.async pipelined (R9, passing).
// ---------------------------------------------------------------------------
#define KT_ 32
#define FS_ 68

__global__ void __launch_bounds__(128, 3) flash_attn()
{
    __shared__ __align__(16) float Ks[2][KT_][FS_];
    __shared__ __align__(16) float Vs[2][KT_][FS_];

    const float* qkv = g_qkv;
    const int tid  = threadIdx.x;
    const int lane = tid & 31;
    const int w    = tid >> 5;
    const int gid  = lane >> 2;
    const int tig  = lane & 3;
    const int qb   = gridDim.x - 1 - blockIdx.x;
    const int b    = blockIdx.y >> 4;
    const int h    = blockIdx.y & 15;
    const size_t base = (size_t)b * T_ * 3 * E_ + (size_t)h * DH_;

#pragma unroll
    for (int i = 0; i < 8; i++) {
        int idx = tid + i * 128;
        int row = idx >> 4;
        int c4  = (idx & 15) << 2;
        cpa16(sptr(&Ks[row >> 5][row & 31][c4]),
              qkv + base + (size_t)(qb * 64 + row) * 3 * E_ + c4);
    }
    asm volatile("cp.async.commit_group;\n" ::: "memory");
    asm volatile("cp.async.wait_group 0;\n" ::: "memory");
    __syncthreads();

    uint32_t qf[8][4];
    {
        const int r0 = w * 16 + gid;
        const int r1 = r0 + 8;
#pragma unroll
        for (int kc = 0; kc < 8; kc++) {
            qf[kc][0] = __float_as_uint(Ks[r0 >> 5][r0 & 31][kc * 8 + tig    ] * 0.125f);
            qf[kc][1] = __float_as_uint(Ks[r1 >> 5][r1 & 31][kc * 8 + tig    ] * 0.125f);
            qf[kc][2] = __float_as_uint(Ks[r0 >> 5][r0 & 31][kc * 8 + tig + 4] * 0.125f);
            qf[kc][3] = __float_as_uint(Ks[r1 >> 5][r1 & 31][kc * 8 + tig + 4] * 0.125f);
        }
    }
    __syncthreads();

    auto issue_kv = [&](int kb, int s) {
#pragma unroll
        for (int i = 0; i < 4; i++) {
            int idx = tid + i * 128;
            int row = idx >> 4;
            int c4  = (idx & 15) << 2;
            size_t tok = base + (size_t)(kb * KT_ + row) * 3 * E_;
            cpa16(sptr(&Ks[s][row][c4]), qkv + tok + E_ + c4);
            cpa16(sptr(&Vs[s][row][c4]), qkv + tok + 2 * E_ + c4);
        }
    };

    issue_kv(0, 0);
    asm volatile("cp.async.commit_group;\n" ::: "memory");

    float m0 = -1e30f, m1 = -1e30f, l0 = 0.f, l1 = 0.f;
    float oacc[8][4];
#pragma unroll
    for (int n = 0; n < 8; n++)
#pragma unroll
        for (int r = 0; r < 4; r++) oacc[n][r] = 0.f;

    const int nkb = 2 * qb + 2;
    for (int kb = 0; kb < nkb; kb++) {
        asm volatile("cp.async.wait_group 0;\n" ::: "memory");
        __syncthreads();
        if (kb + 1 < nkb) {
            issue_kv(kb + 1, (kb + 1) & 1);
            asm volatile("cp.async.commit_group;\n" ::: "memory");
        }
        const float (*Kb)[FS_] = Ks[kb & 1];
        const float (*Vb)[FS_] = Vs[kb & 1];

        float sacc[4][4];
#pragma unroll
        for (int n = 0; n < 4; n++)
#pragma unroll
            for (int r = 0; r < 4; r++) sacc[n][r] = 0.f;

#pragma unroll
        for (int kc = 0; kc < 8; kc++)
#pragma unroll
            for (int n = 0; n < 4; n++) {
                float b0 = Kb[n * 8 + gid][kc * 8 + tig];
                float b1 = Kb[n * 8 + gid][kc * 8 + tig + 4];
                mma_tf32(sacc[n][0], sacc[n][1], sacc[n][2], sacc[n][3],
                         qf[kc][0], qf[kc][1], qf[kc][2], qf[kc][3],
                         __float_as_uint(b0), __float_as_uint(b1));
            }

        if (kb >= 2 * qb) {
            const int rg0 = qb * 64 + w * 16 + gid;
#pragma unroll
            for (int n = 0; n < 4; n++) {
                int c = kb * KT_ + n * 8 + 2 * tig;
                if (c     > rg0    ) sacc[n][0] = -1e30f;
                if (c + 1 > rg0    ) sacc[n][1] = -1e30f;
                if (c     > rg0 + 8) sacc[n][2] = -1e30f;
                if (c + 1 > rg0 + 8) sacc[n][3] = -1e30f;
            }
        }

        float mx0 = -1e30f, mx1 = -1e30f;
#pragma unroll
        for (int n = 0; n < 4; n++) {
            mx0 = fmaxf(mx0, fmaxf(sacc[n][0], sacc[n][1]));
            mx1 = fmaxf(mx1, fmaxf(sacc[n][2], sacc[n][3]));
        }
        mx0 = fmaxf(mx0, __shfl_xor_sync(0xffffffffu, mx0, 1));
        mx0 = fmaxf(mx0, __shfl_xor_sync(0xffffffffu, mx0, 2));
        mx1 = fmaxf(mx1, __shfl_xor_sync(0xffffffffu, mx1, 1));
        mx1 = fmaxf(mx1, __shfl_xor_sync(0xffffffffu, mx1, 2));
        float mn0 = fmaxf(m0, mx0), mn1 = fmaxf(m1, mx1);
        float al0 = __expf(m0 - mn0), al1 = __expf(m1 - mn1);
        m0 = mn0; m1 = mn1;

        float sum0 = 0.f, sum1 = 0.f;
#pragma unroll
        for (int n = 0; n < 4; n++) {
            float p0 = tf32r(__expf(sacc[n][0] - mn0));
            float p1 = tf32r(__expf(sacc[n][1] - mn0));
            float p2 = tf32r(__expf(sacc[n][2] - mn1));
            float p3 = tf32r(__expf(sacc[n][3] - mn1));
            sum0 += p0 + p1; sum1 += p2 + p3;
            sacc[n][0] = p0; sacc[n][1] = p1; sacc[n][2] = p2; sacc[n][3] = p3;
        }
        sum0 += __shfl_xor_sync(0xffffffffu, sum0, 1);
        sum0 += __shfl_xor_sync(0xffffffffu, sum0, 2);
        sum1 += __shfl_xor_sync(0xffffffffu, sum1, 1);
        sum1 += __shfl_xor_sync(0xffffffffu, sum1, 2);
        l0 = l0 * al0 + sum0;
        l1 = l1 * al1 + sum1;
#pragma unroll
        for (int n = 0; n < 8; n++) {
            oacc[n][0] *= al0; oacc[n][1] *= al0;
            oacc[n][2] *= al1; oacc[n][3] *= al1;
        }

        const int src0 = (lane & 28) | (tig >> 1);
        const int src1 = src0 + 2;
        const bool odd = (tig & 1);
#pragma unroll
        for (int kc = 0; kc < 4; kc++) {
            float v00 = __shfl_sync(0xffffffffu, sacc[kc][0], src0);
            float v01 = __shfl_sync(0xffffffffu, sacc[kc][1], src0);
            float v10 = __shfl_sync(0xffffffffu, sacc[kc][0], src1);
            float v11 = __shfl_sync(0xffffffffu, sacc[kc][1], src1);
            float v20 = __shfl_sync(0xffffffffu, sacc[kc][2], src0);
            float v21 = __shfl_sync(0xffffffffu, sacc[kc][3], src0);
            float v30 = __shfl_sync(0xffffffffu, sacc[kc][2], src1);
            float v31 = __shfl_sync(0xffffffffu, sacc[kc][3], src1);
            uint32_t a0 = __float_as_uint(odd ? v01 : v00);
            uint32_t a2 = __float_as_uint(odd ? v11 : v10);
            uint32_t a1 = __float_as_uint(odd ? v21 : v20);
            uint32_t a3 = __float_as_uint(odd ? v31 : v30);
#pragma unroll
            for (int n = 0; n < 8; n++) {
                float b0 = Vb[kc * 8 + tig    ][n * 8 + gid];
                float b1 = Vb[kc * 8 + tig + 4][n * 8 + gid];
                mma_tf32(oacc[n][0], oacc[n][1], oacc[n][2], oacc[n][3],
                         a0, a1, a2, a3,
                         __float_as_uint(b0), __float_as_uint(b1));
            }
        }
    }

    const float inv0 = 1.f / l0, inv1 = 1.f / l1;
    const int row0 = qb * 64 + w * 16 + gid;
#pragma unroll
    for (int n = 0; n < 8; n++) {
        int col = h * DH_ + n * 8 + 2 * tig;
        size_t o0 = ((size_t)b * T_ + row0) * E_ + col;
        size_t o1 = ((size_t)b * T_ + row0 + 8) * E_ + col;
        *reinterpret_cast<float2*>(g_att + o0) =
            make_float2(tf32r(oacc[n][0] * inv0), tf32r(oacc[n][1] * inv0));
        *reinterpret_cast<float2*>(g_att + o1) =
            make_float2(tf32r(oacc[n][2] * inv1), tf32r(oacc[n][3] * inv1));
    }
}

// ---------------------------------------------------------------------------
extern "C" void kernel_launch(void* const* d_in, const int* in_sizes, int n_in,
                              void* d_out, int out_size)
{
    const float* x  = (const float*)d_in[0];
    const float* wi = (const float*)d_in[1];
    const float* bi = (const float*)d_in[2];
    const float* wo = (const float*)d_in[3];
    const float* bo = (const float*)d_in[4];
    const float* wc = (const float*)d_in[5];
    const float* bc = (const float*)d_in[6];
    float* out = (float*)d_out;

    const int M = B_ * T_;  // 8192

    // weight prep
    cvt_w<<<(5 * E_ * E_ / 4 + 255) / 256, 256>>>(wi, wo, wc);
    transpose_wo<<<dim3(32, 32), dim3(32, 8)>>>();
    gemm_wcomb<<<dim3(E_ / 128, E_ / 128), 256>>>();
    bcomb_k<<<E_ / 8, 256>>>(wc, bo, bc);

    // main chain: QKV proj -> attention -> fused (out_proj @ c_proj)
    gemm_in_x<<<dim3(3 * E_ / 128, M / 256), 256>>>(x, bi);
    flash_attn<<<dim3(T_ / 64, B_ * H_), 128>>>();
    gemm_fin<<<dim3(E_ / 128, M / 256), 256>>>(out);
}

// round 13
// speedup vs baseline: 1.5945x; 1.1887x over previous
#include <cuda_runtime.h>
#include <cuda_fp16.h>
#include <math.h>
#include <stdint.h>

#define B_  8
#define T_  1024
#define E_  1024
#define H_  16
#define DH_ 64

// Scratch (__device__ globals: allocation-free rule; zero-initialized)
__device__ float  g_qkv  [(size_t)B_ * T_ * 3 * E_];   // 96 MB (fp16-grid fp32)
__device__ float  g_wo   [(size_t)E_ * E_];            // tf32-rounded
__device__ float  g_wc   [(size_t)E_ * E_];            // tf32-rounded
__device__ float  g_woT  [(size_t)E_ * E_];            // Wo^T
__device__ float  g_wcomb[(size_t)E_ * E_];            // Wc@Wo (tf32 fp32)
__device__ float  g_bcomb[E_];                         // Wc*bo + bc
__device__ float  g_bzero[E_];                         // stays zero
__device__ __align__(16) __half g_xh    [(size_t)B_ * T_ * E_];      // 16 MB
__device__ __align__(16) __half g_wih   [(size_t)3 * E_ * E_];       // 6 MB
__device__ __align__(16) __half g_atth  [(size_t)B_ * T_ * E_];      // 16 MB
__device__ __align__(16) __half g_wcombh[(size_t)E_ * E_];           // 2 MB

// ---------------------------------------------------------------------------
__device__ __forceinline__ float tf32r(float x) {
    uint32_t u;
    asm("cvt.rna.tf32.f32 %0, %1;" : "=r"(u) : "f"(x));
    return __uint_as_float(u);
}
__device__ __forceinline__ float f16r(float x) {
    return __half2float(__float2half_rn(x));
}
__device__ __forceinline__ uint32_t sptr(const void* p) {
    return (uint32_t)__cvta_generic_to_shared(p);
}
__device__ __forceinline__ void cpa16(uint32_t dst, const void* src) {
    asm volatile("cp.async.cg.shared.global [%0], [%1], 16;\n" :: "r"(dst), "l"(src));
}
__device__ __forceinline__ void mma_tf32(
    float& c0, float& c1, float& c2, float& c3,
    uint32_t a0, uint32_t a1, uint32_t a2, uint32_t a3,
    uint32_t b0, uint32_t b1)
{
    asm volatile(
        "mma.sync.aligned.m16n8k8.row.col.f32.tf32.tf32.f32 "
        "{%0,%1,%2,%3},{%4,%5,%6,%7},{%8,%9},{%0,%1,%2,%3};"
        : "+f"(c0), "+f"(c1), "+f"(c2), "+f"(c3)
        : "r"(a0), "r"(a1), "r"(a2), "r"(a3), "r"(b0), "r"(b1));
}
__device__ __forceinline__ void mma_f16(
    float& c0, float& c1, float& c2, float& c3,
    uint32_t a0, uint32_t a1, uint32_t a2, uint32_t a3,
    uint32_t b0, uint32_t b1)
{
    asm volatile(
        "mma.sync.aligned.m16n8k16.row.col.f32.f16.f16.f32 "
        "{%0,%1,%2,%3},{%4,%5,%6,%7},{%8,%9},{%0,%1,%2,%3};"
        : "+f"(c0), "+f"(c1), "+f"(c2), "+f"(c3)
        : "r"(a0), "r"(a1), "r"(a2), "r"(a3), "r"(b0), "r"(b1));
}

// x -> fp16 (rn) --------------------------------------------------------------
__global__ void __launch_bounds__(256) cvt_xh(const float* __restrict__ in) {
    int i = blockIdx.x * blockDim.x + threadIdx.x;
    const int n4 = B_ * T_ * E_ / 4;
    if (i < n4) {
        float4 v = reinterpret_cast<const float4*>(in)[i];
        __half2 h01 = __floats2half2_rn(v.x, v.y);
        __half2 h23 = __floats2half2_rn(v.z, v.w);
        uint2 u;
        u.x = *reinterpret_cast<uint32_t*>(&h01);
        u.y = *reinterpret_cast<uint32_t*>(&h23);
        reinterpret_cast<uint2*>(g_xh)[i] = u;
    }
}

// wi -> half; wo, wc -> tf32-rounded fp32 ------------------------------------
__global__ void __launch_bounds__(256) cvt_w(const float* __restrict__ wi,
                                             const float* __restrict__ wo,
                                             const float* __restrict__ wc) {
    int i = blockIdx.x * blockDim.x + threadIdx.x;
    const int n_i = 3 * E_ * E_ / 4;
    const int n_o = E_ * E_ / 4;
    if (i < n_i) {
        float4 v = reinterpret_cast<const float4*>(wi)[i];
        __half2 h01 = __floats2half2_rn(v.x, v.y);
        __half2 h23 = __floats2half2_rn(v.z, v.w);
        uint2 u;
        u.x = *reinterpret_cast<uint32_t*>(&h01);
        u.y = *reinterpret_cast<uint32_t*>(&h23);
        reinterpret_cast<uint2*>(g_wih)[i] = u;
        return;
    }
    const float4* src;
    float4* dst;
    int j;
    if (i < n_i + n_o)           { src = (const float4*)wo; dst = (float4*)g_wo; j = i - n_i; }
    else if (i < n_i + 2 * n_o)  { src = (const float4*)wc; dst = (float4*)g_wc; j = i - n_i - n_o; }
    else return;
    float4 v = src[j];
    v.x = tf32r(v.x); v.y = tf32r(v.y); v.z = tf32r(v.z); v.w = tf32r(v.w);
    dst[j] = v;
}

// g_wcomb (fp32) -> g_wcombh (half) ------------------------------------------
__global__ void __launch_bounds__(256) cvt_wcomb() {
    int i = blockIdx.x * blockDim.x + threadIdx.x;
    const int n4 = E_ * E_ / 4;
    if (i < n4) {
        float4 v = reinterpret_cast<const float4*>(g_wcomb)[i];
        __half2 h01 = __floats2half2_rn(v.x, v.y);
        __half2 h23 = __floats2half2_rn(v.z, v.w);
        uint2 u;
        u.x = *reinterpret_cast<uint32_t*>(&h01);
        u.y = *reinterpret_cast<uint32_t*>(&h23);
        reinterpret_cast<uint2*>(g_wcombh)[i] = u;
    }
}

// 1024x1024 transpose: g_woT = g_wo^T ----------------------------------------
__global__ void __launch_bounds__(256) transpose_wo() {
    __shared__ float t[32][33];
    int x = blockIdx.x * 32 + threadIdx.x;
    int y = blockIdx.y * 32 + threadIdx.y;
#pragma unroll
    for (int i = 0; i < 32; i += 8)
        t[threadIdx.y + i][threadIdx.x] = g_wo[(size_t)(y + i) * E_ + x];
    __syncthreads();
    x = blockIdx.y * 32 + threadIdx.x;
    y = blockIdx.x * 32 + threadIdx.y;
#pragma unroll
    for (int i = 0; i < 32; i += 8)
        g_woT[(size_t)(y + i) * E_ + x] = t[threadIdx.x][threadIdx.y + i];
}

// b_comb = Wc * bo + bc (fp32, warp per row) ---------------------------------
__global__ void __launch_bounds__(256) bcomb_k(const float* __restrict__ wc,
                                               const float* __restrict__ bo,
                                               const float* __restrict__ bc) {
    int row  = blockIdx.x * 8 + (threadIdx.x >> 5);
    int lane = threadIdx.x & 31;
    const float* wr = wc + (size_t)row * E_;
    float s = 0.f;
    for (int j = lane; j < E_; j += 32) s += wr[j] * bo[j];
#pragma unroll
    for (int o = 16; o; o >>= 1) s += __shfl_xor_sync(0xffffffffu, s, o);
    if (lane == 0) g_bcomb[row] = bc[row] + s;
}

// ---------------------------------------------------------------------------
// Small TF32 GEMM (128x128 tile) — kept for the W_comb prep GEMM only.
// ---------------------------------------------------------------------------
__global__ void __launch_bounds__(256, 2) gemm_wcomb()
{
    const float* A  = g_wc;
    const float* Bm = g_woT;
    const int N = E_, K = E_;
    __shared__ float As[2][128][20];
    __shared__ float Bs[2][128][20];

    const int tid  = threadIdx.x;
    const int lane = tid & 31;
    const int wid  = tid >> 5;
    const int gid  = lane >> 2;
    const int tig  = lane & 3;
    const int wm   = (wid >> 2) * 64;
    const int wn   = (wid & 3) * 32;
    const int bm   = blockIdx.y * 128;
    const int bn   = blockIdx.x * 128;

    float acc[4][4][4];
#pragma unroll
    for (int mt = 0; mt < 4; mt++)
#pragma unroll
        for (int nt = 0; nt < 4; nt++)
#pragma unroll
            for (int r = 0; r < 4; r++) acc[mt][nt][r] = 0.f;

    auto issue = [&](int k0, int s) {
#pragma unroll
        for (int i = 0; i < 2; i++) {
            int idx = tid + i * 256;
            int row = idx >> 2;
            int c4  = (idx & 3) << 2;
            cpa16(sptr(&As[s][row][c4]), A  + (size_t)(bm + row) * K + k0 + c4);
            cpa16(sptr(&Bs[s][row][c4]), Bm + (size_t)(bn + row) * K + k0 + c4);
        }
    };

    issue(0, 0);
    asm volatile("cp.async.commit_group;\n" ::: "memory");

    const int NIT = K / 16;
    for (int it = 0; it < NIT; it++) {
        asm volatile("cp.async.wait_group 0;\n" ::: "memory");
        __syncthreads();
        if (it + 1 < NIT) {
            issue((it + 1) * 16, (it + 1) & 1);
            asm volatile("cp.async.commit_group;\n" ::: "memory");
        }
        const int s = it & 1;
#pragma unroll
        for (int ks = 0; ks < 2; ks++) {
            const int kk = ks * 8 + tig;
            uint32_t a[4][4], b[4][2];
#pragma unroll
            for (int mt = 0; mt < 4; mt++) {
                int r0 = wm + mt * 16 + gid;
                a[mt][0] = __float_as_uint(As[s][r0    ][kk    ]);
                a[mt][1] = __float_as_uint(As[s][r0 + 8][kk    ]);
                a[mt][2] = __float_as_uint(As[s][r0    ][kk + 4]);
                a[mt][3] = __float_as_uint(As[s][r0 + 8][kk + 4]);
            }
#pragma unroll
            for (int nt = 0; nt < 4; nt++) {
                int c0i = wn + nt * 8 + gid;
                b[nt][0] = __float_as_uint(Bs[s][c0i][kk    ]);
                b[nt][1] = __float_as_uint(Bs[s][c0i][kk + 4]);
            }
#pragma unroll
            for (int mt = 0; mt < 4; mt++)
#pragma unroll
                for (int nt = 0; nt < 4; nt++)
                    mma_tf32(acc[mt][nt][0], acc[mt][nt][1], acc[mt][nt][2], acc[mt][nt][3],
                             a[mt][0], a[mt][1], a[mt][2], a[mt][3], b[nt][0], b[nt][1]);
        }
    }

#pragma unroll
    for (int mt = 0; mt < 4; mt++) {
#pragma unroll
        for (int nt = 0; nt < 4; nt++) {
            int row = bm + wm + mt * 16 + gid;
            int col = bn + wn + nt * 8 + tig * 2;
            *reinterpret_cast<float2*>(g_wcomb + (size_t)row * N + col) =
                make_float2(acc[mt][nt][0], acc[mt][nt][1]);
            *reinterpret_cast<float2*>(g_wcomb + (size_t)(row + 8) * N + col) =
                make_float2(acc[mt][nt][2], acc[mt][nt][3]);
        }
    }
}

// ---------------------------------------------------------------------------
// Big FP16 GEMM: C[M,N] = A[M,K] @ B[N,K]^T + bias[N], fp32 accumulate.
// 256x128 CTA tile, 8 warps 4(M)x2(N) of 64x64, BK=16 = one m16n8k16 step.
// Half smem rows, 48B stride: banks (12*gid + tig) mod 32 = full permutation.
// 2-stage cp.async, one __syncthreads per K-step. Static smem 36,864 B.
// ---------------------------------------------------------------------------
__device__ __forceinline__ void gemm_f16_big(
    const __half* __restrict__ A, const __half* __restrict__ Bm,
    const float* __restrict__ bias, float* __restrict__ C,
    int N, int K, int round_q)
{
    __shared__ __half As[2][256][24];
    __shared__ __half Bs[2][128][24];

    const int tid  = threadIdx.x;
    const int lane = tid & 31;
    const int wid  = tid >> 5;
    const int gid  = lane >> 2;
    const int tig  = lane & 3;
    const int wm   = (wid >> 1) * 64;
    const int wn   = (wid & 1) * 64;
    const int bm   = blockIdx.y * 256;
    const int bn   = blockIdx.x * 128;

    float acc[4][8][4];
#pragma unroll
    for (int mt = 0; mt < 4; mt++)
#pragma unroll
        for (int nt = 0; nt < 8; nt++)
#pragma unroll
            for (int r = 0; r < 4; r++) acc[mt][nt][r] = 0.f;

    auto issue = [&](int k0, int s) {
#pragma unroll
        for (int i = 0; i < 2; i++) {            // A: 256 rows x 2 chunks
            int idx = tid + i * 256;             // 0..511
            int row = idx >> 1;                  // 0..255
            int ci  = idx & 1;                   // 16B chunk (8 halves)
            cpa16(sptr(&As[s][row][ci * 8]),
                  A + (size_t)(bm + row) * K + k0 + ci * 8);
        }
        {                                        // B: 128 rows x 2 chunks
            int row = tid >> 1;
            int ci  = tid & 1;
            cpa16(sptr(&Bs[s][row][ci * 8]),
                  Bm + (size_t)(bn + row) * K + k0 + ci * 8);
        }
    };

    issue(0, 0);
    asm volatile("cp.async.commit_group;\n" ::: "memory");

    const int NIT = K / 16;
    for (int it = 0; it < NIT; it++) {
        asm volatile("cp.async.wait_group 0;\n" ::: "memory");
        __syncthreads();
        if (it + 1 < NIT) {
            issue((it + 1) * 16, (it + 1) & 1);
            asm volatile("cp.async.commit_group;\n" ::: "memory");
        }

        const int s = it & 1;
        uint32_t a[4][4], b[8][2];
#pragma unroll
        for (int mt = 0; mt < 4; mt++) {
            int r0 = wm + mt * 16 + gid;
            int r1 = r0 + 8;
            a[mt][0] = *reinterpret_cast<const uint32_t*>(&As[s][r0][2 * tig    ]);
            a[mt][1] = *reinterpret_cast<const uint32_t*>(&As[s][r1][2 * tig    ]);
            a[mt][2] = *reinterpret_cast<const uint32_t*>(&As[s][r0][2 * tig + 8]);
            a[mt][3] = *reinterpret_cast<const uint32_t*>(&As[s][r1][2 * tig + 8]);
        }
#pragma unroll
        for (int nt = 0; nt < 8; nt++) {
            int c0i = wn + nt * 8 + gid;
            b[nt][0] = *reinterpret_cast<const uint32_t*>(&Bs[s][c0i][2 * tig    ]);
            b[nt][1] = *reinterpret_cast<const uint32_t*>(&Bs[s][c0i][2 * tig + 8]);
        }
#pragma unroll
        for (int mt = 0; mt < 4; mt++)
#pragma unroll
            for (int nt = 0; nt < 8; nt++)
                mma_f16(acc[mt][nt][0], acc[mt][nt][1], acc[mt][nt][2], acc[mt][nt][3],
                        a[mt][0], a[mt][1], a[mt][2], a[mt][3], b[nt][0], b[nt][1]);
    }

#pragma unroll
    for (int mt = 0; mt < 4; mt++) {
#pragma unroll
        for (int nt = 0; nt < 8; nt++) {
            int row = bm + wm + mt * 16 + gid;
            int col = bn + wn + nt * 8 + tig * 2;
            float bv0 = bias[col], bv1 = bias[col + 1];
            float v0 = acc[mt][nt][0] + bv0;
            float v1 = acc[mt][nt][1] + bv1;
            float v2 = acc[mt][nt][2] + bv0;
            float v3 = acc[mt][nt][3] + bv1;
            if (round_q) {   // keep on fp16 grid -> downstream tf32 MMA lossless
                v0 = f16r(v0); v1 = f16r(v1); v2 = f16r(v2); v3 = f16r(v3);
            }
            *reinterpret_cast<float2*>(C + (size_t)row * N + col) = make_float2(v0, v1);
            *reinterpret_cast<float2*>(C + (size_t)(row + 8) * N + col) = make_float2(v2, v3);
        }
    }
}

__global__ void __launch_bounds__(256, 1) gemm_in_h(const float* __restrict__ bi) {
    gemm_f16_big(g_xh, g_wih, bi, g_qkv, 3 * E_, E_, 1);
}
__global__ void __launch_bounds__(256, 1) gemm_fin_h(float* __restrict__ out) {
    gemm_f16_big(g_atth, g_wcombh, g_bcomb, out, E_, E_, 0);
}

// ---------------------------------------------------------------------------
// Tensor-core causal flash attention (R9, passing) — epilogue now writes
// g_atth as half2 (the fp16 rounding the final GEMM needs; halves traffic).
// ---------------------------------------------------------------------------
#define KT_ 32
#define FS_ 68

__global__ void __launch_bounds__(128, 3) flash_attn()
{
    __shared__ __align__(16) float Ks[2][KT_][FS_];
    __shared__ __align__(16) float Vs[2][KT_][FS_];

    const float* qkv = g_qkv;
    const int tid  = threadIdx.x;
    const int lane = tid & 31;
    const int w    = tid >> 5;
    const int gid  = lane >> 2;
    const int tig  = lane & 3;
    const int qb   = gridDim.x - 1 - blockIdx.x;
    const int b    = blockIdx.y >> 4;
    const int h    = blockIdx.y & 15;
    const size_t base = (size_t)b * T_ * 3 * E_ + (size_t)h * DH_;

#pragma unroll
    for (int i = 0; i < 8; i++) {
        int idx = tid + i * 128;
        int row = idx >> 4;
        int c4  = (idx & 15) << 2;
        cpa16(sptr(&Ks[row >> 5][row & 31][c4]),
              qkv + base + (size_t)(qb * 64 + row) * 3 * E_ + c4);
    }
    asm volatile("cp.async.commit_group;\n" ::: "memory");
    asm volatile("cp.async.wait_group 0;\n" ::: "memory");
    __syncthreads();

    uint32_t qf[8][4];
    {
        const int r0 = w * 16 + gid;
        const int r1 = r0 + 8;
#pragma unroll
        for (int kc = 0; kc < 8; kc++) {
            qf[kc][0] = __float_as_uint(Ks[r0 >> 5][r0 & 31][kc * 8 + tig    ] * 0.125f);
            qf[kc][1] = __float_as_uint(Ks[r1 >> 5][r1 & 31][kc * 8 + tig    ] * 0.125f);
            qf[kc][2] = __float_as_uint(Ks[r0 >> 5][r0 & 31][kc * 8 + tig + 4] * 0.125f);
            qf[kc][3] = __float_as_uint(Ks[r1 >> 5][r1 & 31][kc * 8 + tig + 4] * 0.125f);
        }
    }
    __syncthreads();

    auto issue_kv = [&](int kb, int s) {
#pragma unroll
        for (int i = 0; i < 4; i++) {
            int idx = tid + i * 128;
            int row = idx >> 4;
            int c4  = (idx & 15) << 2;
            size_t tok = base + (size_t)(kb * KT_ + row) * 3 * E_;
            cpa16(sptr(&Ks[s][row][c4]), qkv + tok + E_ + c4);
            cpa16(sptr(&Vs[s][row][c4]), qkv + tok + 2 * E_ + c4);
        }
    };

    issue_kv(0, 0);
    asm volatile("cp.async.commit_group;\n" ::: "memory");

    float m0 = -1e30f, m1 = -1e30f, l0 = 0.f, l1 = 0.f;
    float oacc[8][4];
#pragma unroll
    for (int n = 0; n < 8; n++)
#pragma unroll
        for (int r = 0; r < 4; r++) oacc[n][r] = 0.f;

    const int nkb = 2 * qb + 2;
    for (int kb = 0; kb < nkb; kb++) {
        asm volatile("cp.async.wait_group 0;\n" ::: "memory");
        __syncthreads();
        if (kb + 1 < nkb) {
            issue_kv(kb + 1, (kb + 1) & 1);
            asm volatile("cp.async.commit_group;\n" ::: "memory");
        }
        const float (*Kb)[FS_] = Ks[kb & 1];
        const float (*Vb)[FS_] = Vs[kb & 1];

        float sacc[4][4];
#pragma unroll
        for (int n = 0; n < 4; n++)
#pragma unroll
            for (int r = 0; r < 4; r++) sacc[n][r] = 0.f;

#pragma unroll
        for (int kc = 0; kc < 8; kc++)
#pragma unroll
            for (int n = 0; n < 4; n++) {
                float b0 = Kb[n * 8 + gid][kc * 8 + tig];
                float b1 = Kb[n * 8 + gid][kc * 8 + tig + 4];
                mma_tf32(sacc[n][0], sacc[n][1], sacc[n][2], sacc[n][3],
                         qf[kc][0], qf[kc][1], qf[kc][2], qf[kc][3],
                         __float_as_uint(b0), __float_as_uint(b1));
            }

        if (kb >= 2 * qb) {
            const int rg0 = qb * 64 + w * 16 + gid;
#pragma unroll
            for (int n = 0; n < 4; n++) {
                int c = kb * KT_ + n * 8 + 2 * tig;
                if (c     > rg0    ) sacc[n][0] = -1e30f;
                if (c + 1 > rg0    ) sacc[n][1] = -1e30f;
                if (c     > rg0 + 8) sacc[n][2] = -1e30f;
                if (c + 1 > rg0 + 8) sacc[n][3] = -1e30f;
            }
        }

        float mx0 = -1e30f, mx1 = -1e30f;
#pragma unroll
        for (int n = 0; n < 4; n++) {
            mx0 = fmaxf(mx0, fmaxf(sacc[n][0], sacc[n][1]));
            mx1 = fmaxf(mx1, fmaxf(sacc[n][2], sacc[n][3]));
        }
        mx0 = fmaxf(mx0, __shfl_xor_sync(0xffffffffu, mx0, 1));
        mx0 = fmaxf(mx0, __shfl_xor_sync(0xffffffffu, mx0, 2));
        mx1 = fmaxf(mx1, __shfl_xor_sync(0xffffffffu, mx1, 1));
        mx1 = fmaxf(mx1, __shfl_xor_sync(0xffffffffu, mx1, 2));
        float mn0 = fmaxf(m0, mx0), mn1 = fmaxf(m1, mx1);
        float al0 = __expf(m0 - mn0), al1 = __expf(m1 - mn1);
        m0 = mn0; m1 = mn1;

        float sum0 = 0.f, sum1 = 0.f;
#pragma unroll
        for (int n = 0; n < 4; n++) {
            float p0 = tf32r(__expf(sacc[n][0] - mn0));
            float p1 = tf32r(__expf(sacc[n][1] - mn0));
            float p2 = tf32r(__expf(sacc[n][2] - mn1));
            float p3 = tf32r(__expf(sacc[n][3] - mn1));
            sum0 += p0 + p1; sum1 += p2 + p3;
            sacc[n][0] = p0; sacc[n][1] = p1; sacc[n][2] = p2; sacc[n][3] = p3;
        }
        sum0 += __shfl_xor_sync(0xffffffffu, sum0, 1);
        sum0 += __shfl_xor_sync(0xffffffffu, sum0, 2);
        sum1 += __shfl_xor_sync(0xffffffffu, sum1, 1);
        sum1 += __shfl_xor_sync(0xffffffffu, sum1, 2);
        l0 = l0 * al0 + sum0;
        l1 = l1 * al1 + sum1;
#pragma unroll
        for (int n = 0; n < 8; n++) {
            oacc[n][0] *= al0; oacc[n][1] *= al0;
            oacc[n][2] *= al1; oacc[n][3] *= al1;
        }

        const int src0 = (lane & 28) | (tig >> 1);
        const int src1 = src0 + 2;
        const bool odd = (tig & 1);
#pragma unroll
        for (int kc = 0; kc < 4; kc++) {
            float v00 = __shfl_sync(0xffffffffu, sacc[kc][0], src0);
            float v01 = __shfl_sync(0xffffffffu, sacc[kc][1], src0);
            float v10 = __shfl_sync(0xffffffffu, sacc[kc][0], src1);
            float v11 = __shfl_sync(0xffffffffu, sacc[kc][1], src1);
            float v20 = __shfl_sync(0xffffffffu, sacc[kc][2], src0);
            float v21 = __shfl_sync(0xffffffffu, sacc[kc][3], src0);
            float v30 = __shfl_sync(0xffffffffu, sacc[kc][2], src1);
            float v31 = __shfl_sync(0xffffffffu, sacc[kc][3], src1);
            uint32_t a0 = __float_as_uint(odd ? v01 : v00);
            uint32_t a2 = __float_as_uint(odd ? v11 : v10);
            uint32_t a1 = __float_as_uint(odd ? v21 : v20);
            uint32_t a3 = __float_as_uint(odd ? v31 : v30);
#pragma unroll
            for (int n = 0; n < 8; n++) {
                float b0 = Vb[kc * 8 + tig    ][n * 8 + gid];
                float b1 = Vb[kc * 8 + tig + 4][n * 8 + gid];
                mma_tf32(oacc[n][0], oacc[n][1], oacc[n][2], oacc[n][3],
                         a0, a1, a2, a3,
                         __float_as_uint(b0), __float_as_uint(b1));
            }
        }
    }

    // ---- epilogue: normalize, write att as fp16 half2 [B,T,E] ----
    const float inv0 = 1.f / l0, inv1 = 1.f / l1;
    const int row0 = qb * 64 + w * 16 + gid;
#pragma unroll
    for (int n = 0; n < 8; n++) {
        int col = h * DH_ + n * 8 + 2 * tig;
        size_t o0 = ((size_t)b * T_ + row0) * E_ + col;
        size_t o1 = ((size_t)b * T_ + row0 + 8) * E_ + col;
        *reinterpret_cast<__half2*>(&g_atth[o0]) =
            __floats2half2_rn(oacc[n][0] * inv0, oacc[n][1] * inv0);
        *reinterpret_cast<__half2*>(&g_atth[o1]) =
            __floats2half2_rn(oacc[n][2] * inv1, oacc[n][3] * inv1);
    }
}

// ---------------------------------------------------------------------------
extern "C" void kernel_launch(void* const* d_in, const int* in_sizes, int n_in,
                              void* d_out, int out_size)
{
    const float* x  = (const float*)d_in[0];
    const float* wi = (const float*)d_in[1];
    const float* bi = (const float*)d_in[2];
    const float* wo = (const float*)d_in[3];
    const float* bo = (const float*)d_in[4];
    const float* wc = (const float*)d_in[5];
    const float* bc = (const float*)d_in[6];
    float* out = (float*)d_out;

    const int M = B_ * T_;  // 8192

    // weight/input prep
    cvt_xh<<<(B_ * T_ * E_ / 4 + 255) / 256, 256>>>(x);
    cvt_w<<<(5 * E_ * E_ / 4 + 255) / 256, 256>>>(wi, wo, wc);
    transpose_wo<<<dim3(32, 32), dim3(32, 8)>>>();
    gemm_wcomb<<<dim3(E_ / 128, E_ / 128), 256>>>();
    cvt_wcomb<<<(E_ * E_ / 4 + 255) / 256, 256>>>();
    bcomb_k<<<E_ / 8, 256>>>(wc, bo, bc);

    // main chain: QKV proj (fp16) -> attention -> fused projection (fp16)
    gemm_in_h<<<dim3(3 * E_ / 128, M / 256), 256>>>(bi);
    flash_attn<<<dim3(T_ / 64, B_ * H_), 128>>>();
    gemm_fin_h<<<dim3(E_ / 128, M / 256), 256>>>(out);
}

// round 14
// speedup vs baseline: 1.6355x; 1.0258x over previous
#include <cuda_runtime.h>
#include <cuda_fp16.h>
#include <math.h>
#include <stdint.h>

#define B_  8
#define T_  1024
#define E_  1024
#define H_  16
#define DH_ 64

// Scratch (__device__ globals: allocation-free rule; zero-initialized)
__device__ float  g_qkv  [(size_t)B_ * T_ * 3 * E_];   // 96 MB (fp16-grid fp32)
__device__ float  g_bcomb[E_];                         // Wc*bo + bc
__device__ __align__(16) __half g_xh    [(size_t)B_ * T_ * E_];      // 16 MB
__device__ __align__(16) __half g_wih   [(size_t)3 * E_ * E_];       // 6 MB
__device__ __align__(16) __half g_wch   [(size_t)E_ * E_];           // 2 MB
__device__ __align__(16) __half g_woTh  [(size_t)E_ * E_];           // 2 MB
__device__ __align__(16) __half g_atth  [(size_t)B_ * T_ * E_];      // 16 MB
__device__ __align__(16) __half g_wcombh[(size_t)E_ * E_];           // 2 MB

// ---------------------------------------------------------------------------
__device__ __forceinline__ float tf32r(float x) {
    uint32_t u;
    asm("cvt.rna.tf32.f32 %0, %1;" : "=r"(u) : "f"(x));
    return __uint_as_float(u);
}
__device__ __forceinline__ float f16r(float x) {
    return __half2float(__float2half_rn(x));
}
__device__ __forceinline__ uint32_t sptr(const void* p) {
    return (uint32_t)__cvta_generic_to_shared(p);
}
__device__ __forceinline__ void cpa16(uint32_t dst, const void* src) {
    asm volatile("cp.async.cg.shared.global [%0], [%1], 16;\n" :: "r"(dst), "l"(src));
}
__device__ __forceinline__ void mma_tf32(
    float& c0, float& c1, float& c2, float& c3,
    uint32_t a0, uint32_t a1, uint32_t a2, uint32_t a3,
    uint32_t b0, uint32_t b1)
{
    asm volatile(
        "mma.sync.aligned.m16n8k8.row.col.f32.tf32.tf32.f32 "
        "{%0,%1,%2,%3},{%4,%5,%6,%7},{%8,%9},{%0,%1,%2,%3};"
        : "+f"(c0), "+f"(c1), "+f"(c2), "+f"(c3)
        : "r"(a0), "r"(a1), "r"(a2), "r"(a3), "r"(b0), "r"(b1));
}
__device__ __forceinline__ void mma_f16(
    float& c0, float& c1, float& c2, float& c3,
    uint32_t a0, uint32_t a1, uint32_t a2, uint32_t a3,
    uint32_t b0, uint32_t b1)
{
    asm volatile(
        "mma.sync.aligned.m16n8k16.row.col.f32.f16.f16.f32 "
        "{%0,%1,%2,%3},{%4,%5,%6,%7},{%8,%9},{%0,%1,%2,%3};"
        : "+f"(c0), "+f"(c1), "+f"(c2), "+f"(c3)
        : "r"(a0), "r"(a1), "r"(a2), "r"(a3), "r"(b0), "r"(b1));
}

// x -> fp16 (rn) --------------------------------------------------------------
__global__ void __launch_bounds__(256) cvt_xh(const float* __restrict__ in) {
    int i = blockIdx.x * blockDim.x + threadIdx.x;
    const int n4 = B_ * T_ * E_ / 4;
    if (i < n4) {
        float4 v = reinterpret_cast<const float4*>(in)[i];
        __half2 h01 = __floats2half2_rn(v.x, v.y);
        __half2 h23 = __floats2half2_rn(v.z, v.w);
        uint2 u;
        u.x = *reinterpret_cast<uint32_t*>(&h01);
        u.y = *reinterpret_cast<uint32_t*>(&h23);
        reinterpret_cast<uint2*>(g_xh)[i] = u;
    }
}

// wi -> half; wc -> half ------------------------------------------------------
__global__ void __launch_bounds__(256) cvt_w(const float* __restrict__ wi,
                                             const float* __restrict__ wc) {
    int i = blockIdx.x * blockDim.x + threadIdx.x;
    const int n_i = 3 * E_ * E_ / 4;
    const int n_o = E_ * E_ / 4;
    const float4* src;
    __half* dsth;
    int j;
    if (i < n_i)             { src = (const float4*)wi; dsth = g_wih; j = i; }
    else if (i < n_i + n_o)  { src = (const float4*)wc; dsth = g_wch; j = i - n_i; }
    else return;
    float4 v = src[j];
    __half2 h01 = __floats2half2_rn(v.x, v.y);
    __half2 h23 = __floats2half2_rn(v.z, v.w);
    uint2 u;
    u.x = *reinterpret_cast<uint32_t*>(&h01);
    u.y = *reinterpret_cast<uint32_t*>(&h23);
    reinterpret_cast<uint2*>(dsth)[j] = u;
}

// 1024x1024 transpose + half convert: g_woTh = half(Wo^T) --------------------
__global__ void __launch_bounds__(256) transpose_wo(const float* __restrict__ wo) {
    __shared__ float t[32][33];
    int x = blockIdx.x * 32 + threadIdx.x;
    int y = blockIdx.y * 32 + threadIdx.y;
#pragma unroll
    for (int i = 0; i < 32; i += 8)
        t[threadIdx.y + i][threadIdx.x] = wo[(size_t)(y + i) * E_ + x];
    __syncthreads();
    x = blockIdx.y * 32 + threadIdx.x;
    y = blockIdx.x * 32 + threadIdx.y;
#pragma unroll
    for (int i = 0; i < 32; i += 8)
        g_woTh[(size_t)(y + i) * E_ + x] = __float2half_rn(t[threadIdx.x][threadIdx.y + i]);
}

// b_comb = Wc * bo + bc (fp32, warp per row) ---------------------------------
__global__ void __launch_bounds__(256) bcomb_k(const float* __restrict__ wc,
                                               const float* __restrict__ bo,
                                               const float* __restrict__ bc) {
    int row  = blockIdx.x * 8 + (threadIdx.x >> 5);
    int lane = threadIdx.x & 31;
    const float* wr = wc + (size_t)row * E_;
    float s = 0.f;
    for (int j = lane; j < E_; j += 32) s += wr[j] * bo[j];
#pragma unroll
    for (int o = 16; o; o >>= 1) s += __shfl_xor_sync(0xffffffffu, s, o);
    if (lane == 0) g_bcomb[row] = bc[row] + s;
}

// ---------------------------------------------------------------------------
// FP16 wcomb GEMM: g_wcombh = half(Wc @ Wo) via A=g_wch, B=g_woTh.
// 128x128 tile, 8 warps 2(M)x4(N), warp 64x32. BK=16, 48B half rows
// (banks (12g+t) mod 32 permutation). 2-stage, 24KB smem -> 2 CTAs/SM.
// ---------------------------------------------------------------------------
__global__ void __launch_bounds__(256, 2) gemm_wcomb_h()
{
    const __half* A  = g_wch;
    const __half* Bm = g_woTh;
    const int N = E_, K = E_;
    __shared__ __half As[2][128][24];
    __shared__ __half Bs[2][128][24];

    const int tid  = threadIdx.x;
    const int lane = tid & 31;
    const int wid  = tid >> 5;
    const int gid  = lane >> 2;
    const int tig  = lane & 3;
    const int wm   = (wid >> 2) * 64;
    const int wn   = (wid & 3) * 32;
    const int bm   = blockIdx.y * 128;
    const int bn   = blockIdx.x * 128;

    float acc[4][4][4];
#pragma unroll
    for (int mt = 0; mt < 4; mt++)
#pragma unroll
        for (int nt = 0; nt < 4; nt++)
#pragma unroll
            for (int r = 0; r < 4; r++) acc[mt][nt][r] = 0.f;

    auto issue = [&](int k0, int s) {
        int row = tid >> 1;
        int ci  = tid & 1;
        cpa16(sptr(&As[s][row][ci * 8]), A  + (size_t)(bm + row) * K + k0 + ci * 8);
        cpa16(sptr(&Bs[s][row][ci * 8]), Bm + (size_t)(bn + row) * K + k0 + ci * 8);
    };

    issue(0, 0);
    asm volatile("cp.async.commit_group;\n" ::: "memory");

    const int NIT = K / 16;
    for (int it = 0; it < NIT; it++) {
        asm volatile("cp.async.wait_group 0;\n" ::: "memory");
        __syncthreads();
        if (it + 1 < NIT) {
            issue((it + 1) * 16, (it + 1) & 1);
            asm volatile("cp.async.commit_group;\n" ::: "memory");
        }
        const int s = it & 1;
        uint32_t a[4][4], b[4][2];
#pragma unroll
        for (int mt = 0; mt < 4; mt++) {
            int r0 = wm + mt * 16 + gid;
            int r1 = r0 + 8;
            a[mt][0] = *reinterpret_cast<const uint32_t*>(&As[s][r0][2 * tig    ]);
            a[mt][1] = *reinterpret_cast<const uint32_t*>(&As[s][r1][2 * tig    ]);
            a[mt][2] = *reinterpret_cast<const uint32_t*>(&As[s][r0][2 * tig + 8]);
            a[mt][3] = *reinterpret_cast<const uint32_t*>(&As[s][r1][2 * tig + 8]);
        }
#pragma unroll
        for (int nt = 0; nt < 4; nt++) {
            int c0i = wn + nt * 8 + gid;
            b[nt][0] = *reinterpret_cast<const uint32_t*>(&Bs[s][c0i][2 * tig    ]);
            b[nt][1] = *reinterpret_cast<const uint32_t*>(&Bs[s][c0i][2 * tig + 8]);
        }
#pragma unroll
        for (int mt = 0; mt < 4; mt++)
#pragma unroll
            for (int nt = 0; nt < 4; nt++)
                mma_f16(acc[mt][nt][0], acc[mt][nt][1], acc[mt][nt][2], acc[mt][nt][3],
                        a[mt][0], a[mt][1], a[mt][2], a[mt][3], b[nt][0], b[nt][1]);
    }

#pragma unroll
    for (int mt = 0; mt < 4; mt++) {
#pragma unroll
        for (int nt = 0; nt < 4; nt++) {
            int row = bm + wm + mt * 16 + gid;
            int col = bn + wn + nt * 8 + tig * 2;
            *reinterpret_cast<__half2*>(&g_wcombh[(size_t)row * N + col]) =
                __floats2half2_rn(acc[mt][nt][0], acc[mt][nt][1]);
            *reinterpret_cast<__half2*>(&g_wcombh[(size_t)(row + 8) * N + col]) =
                __floats2half2_rn(acc[mt][nt][2], acc[mt][nt][3]);
        }
    }
}

// ---------------------------------------------------------------------------
// Big FP16 GEMM, 3-stage pipeline: C[M,N] = A @ B^T + bias, fp32 accumulate.
// 256x128 CTA tile, 8 warps 4(M)x2(N) of 64x64, BK=16.
// Smem stride 16 halves (32B rows) + 16B-chunk XOR swizzle ci^(row&1):
// 36 KB static (3 stages). Fragment LDS is 2-way bank-conflicted (accepted).
// Prefetch distance 2, wait_group 1 -> ~2 compute iters cover DRAM latency.
// ---------------------------------------------------------------------------
__device__ __forceinline__ void gemm_f16_big3(
    const __half* __restrict__ A, const __half* __restrict__ Bm,
    const float* __restrict__ bias, float* __restrict__ C,
    int N, int K, int round_q)
{
    __shared__ __half As[3][256][16];
    __shared__ __half Bs[3][128][16];

    const int tid  = threadIdx.x;
    const int lane = tid & 31;
    const int wid  = tid >> 5;
    const int gid  = lane >> 2;
    const int tig  = lane & 3;
    const int wm   = (wid >> 1) * 64;
    const int wn   = (wid & 1) * 64;
    const int bm   = blockIdx.y * 256;
    const int bn   = blockIdx.x * 128;

    float acc[4][8][4];
#pragma unroll
    for (int mt = 0; mt < 4; mt++)
#pragma unroll
        for (int nt = 0; nt < 8; nt++)
#pragma unroll
            for (int r = 0; r < 4; r++) acc[mt][nt][r] = 0.f;

    auto issue = [&](int k0, int s) {
#pragma unroll
        for (int i = 0; i < 2; i++) {            // A: 256 rows x 2 chunks
            int idx = tid + i * 256;
            int row = idx >> 1;
            int ci  = idx & 1;
            cpa16(sptr(&As[s][row][(ci ^ (row & 1)) * 8]),
                  A + (size_t)(bm + row) * K + k0 + ci * 8);
        }
        {                                        // B: 128 rows x 2 chunks
            int row = tid >> 1;
            int ci  = tid & 1;
            cpa16(sptr(&Bs[s][row][(ci ^ (row & 1)) * 8]),
                  Bm + (size_t)(bn + row) * K + k0 + ci * 8);
        }
    };

    issue(0, 0);
    asm volatile("cp.async.commit_group;\n" ::: "memory");
    issue(16, 1);
    asm volatile("cp.async.commit_group;\n" ::: "memory");

    const int NIT = K / 16;
    int sc = 0;
    for (int it = 0; it < NIT; it++) {
        if (it + 1 < NIT) {
            asm volatile("cp.async.wait_group 1;\n" ::: "memory");
        } else {
            asm volatile("cp.async.wait_group 0;\n" ::: "memory");
        }
        __syncthreads();
        if (it + 2 < NIT) {
            int s2 = sc + 2; if (s2 >= 3) s2 -= 3;
            issue((it + 2) * 16, s2);
            asm volatile("cp.async.commit_group;\n" ::: "memory");
        }

        uint32_t a[4][4], b[8][2];
#pragma unroll
        for (int mt = 0; mt < 4; mt++) {
            int r0 = wm + mt * 16 + gid;
            int r1 = r0 + 8;                     // same parity as r0
            int p  = (r0 & 1) * 8;               // chunk0 halves offset
            a[mt][0] = *reinterpret_cast<const uint32_t*>(&As[sc][r0][p       + 2 * tig]);
            a[mt][1] = *reinterpret_cast<const uint32_t*>(&As[sc][r1][p       + 2 * tig]);
            a[mt][2] = *reinterpret_cast<const uint32_t*>(&As[sc][r0][(8 - p) + 2 * tig]);
            a[mt][3] = *reinterpret_cast<const uint32_t*>(&As[sc][r1][(8 - p) + 2 * tig]);
        }
#pragma unroll
        for (int nt = 0; nt < 8; nt++) {
            int c0i = wn + nt * 8 + gid;
            int p   = (c0i & 1) * 8;
            b[nt][0] = *reinterpret_cast<const uint32_t*>(&Bs[sc][c0i][p       + 2 * tig]);
            b[nt][1] = *reinterpret_cast<const uint32_t*>(&Bs[sc][c0i][(8 - p) + 2 * tig]);
        }
#pragma unroll
        for (int mt = 0; mt < 4; mt++)
#pragma unroll
            for (int nt = 0; nt < 8; nt++)
                mma_f16(acc[mt][nt][0], acc[mt][nt][1], acc[mt][nt][2], acc[mt][nt][3],
                        a[mt][0], a[mt][1], a[mt][2], a[mt][3], b[nt][0], b[nt][1]);

        sc = (sc == 2) ? 0 : sc + 1;
    }

#pragma unroll
    for (int mt = 0; mt < 4; mt++) {
#pragma unroll
        for (int nt = 0; nt < 8; nt++) {
            int row = bm + wm + mt * 16 + gid;
            int col = bn + wn + nt * 8 + tig * 2;
            float bv0 = bias[col], bv1 = bias[col + 1];
            float v0 = acc[mt][nt][0] + bv0;
            float v1 = acc[mt][nt][1] + bv1;
            float v2 = acc[mt][nt][2] + bv0;
            float v3 = acc[mt][nt][3] + bv1;
            if (round_q) {   // keep on fp16 grid -> downstream tf32 MMA lossless
                v0 = f16r(v0); v1 = f16r(v1); v2 = f16r(v2); v3 = f16r(v3);
            }
            *reinterpret_cast<float2*>(C + (size_t)row * N + col) = make_float2(v0, v1);
            *reinterpret_cast<float2*>(C + (size_t)(row + 8) * N + col) = make_float2(v2, v3);
        }
    }
}

__global__ void __launch_bounds__(256, 1) gemm_in_h(const float* __restrict__ bi) {
    gemm_f16_big3(g_xh, g_wih, bi, g_qkv, 3 * E_, E_, 1);
}
__global__ void __launch_bounds__(256, 1) gemm_fin_h(float* __restrict__ out) {
    gemm_f16_big3(g_atth, g_wcombh, g_bcomb, out, E_, E_, 0);
}

// ---------------------------------------------------------------------------
// Tensor-core causal flash attention (R13, passing).
// ---------------------------------------------------------------------------
#define KT_ 32
#define FS_ 68

__global__ void __launch_bounds__(128, 3) flash_attn()
{
    __shared__ __align__(16) float Ks[2][KT_][FS_];
    __shared__ __align__(16) float Vs[2][KT_][FS_];

    const float* qkv = g_qkv;
    const int tid  = threadIdx.x;
    const int lane = tid & 31;
    const int w    = tid >> 5;
    const int gid  = lane >> 2;
    const int tig  = lane & 3;
    const int qb   = gridDim.x - 1 - blockIdx.x;
    const int b    = blockIdx.y >> 4;
    const int h    = blockIdx.y & 15;
    const size_t base = (size_t)b * T_ * 3 * E_ + (size_t)h * DH_;

#pragma unroll
    for (int i = 0; i < 8; i++) {
        int idx = tid + i * 128;
        int row = idx >> 4;
        int c4  = (idx & 15) << 2;
        cpa16(sptr(&Ks[row >> 5][row & 31][c4]),
              qkv + base + (size_t)(qb * 64 + row) * 3 * E_ + c4);
    }
    asm volatile("cp.async.commit_group;\n" ::: "memory");
    asm volatile("cp.async.wait_group 0;\n" ::: "memory");
    __syncthreads();

    uint32_t qf[8][4];
    {
        const int r0 = w * 16 + gid;
        const int r1 = r0 + 8;
#pragma unroll
        for (int kc = 0; kc < 8; kc++) {
            qf[kc][0] = __float_as_uint(Ks[r0 >> 5][r0 & 31][kc * 8 + tig    ] * 0.125f);
            qf[kc][1] = __float_as_uint(Ks[r1 >> 5][r1 & 31][kc * 8 + tig    ] * 0.125f);
            qf[kc][2] = __float_as_uint(Ks[r0 >> 5][r0 & 31][kc * 8 + tig + 4] * 0.125f);
            qf[kc][3] = __float_as_uint(Ks[r1 >> 5][r1 & 31][kc * 8 + tig + 4] * 0.125f);
        }
    }
    __syncthreads();

    auto issue_kv = [&](int kb, int s) {
#pragma unroll
        for (int i = 0; i < 4; i++) {
            int idx = tid + i * 128;
            int row = idx >> 4;
            int c4  = (idx & 15) << 2;
            size_t tok = base + (size_t)(kb * KT_ + row) * 3 * E_;
            cpa16(sptr(&Ks[s][row][c4]), qkv + tok + E_ + c4);
            cpa16(sptr(&Vs[s][row][c4]), qkv + tok + 2 * E_ + c4);
        }
    };

    issue_kv(0, 0);
    asm volatile("cp.async.commit_group;\n" ::: "memory");

    float m0 = -1e30f, m1 = -1e30f, l0 = 0.f, l1 = 0.f;
    float oacc[8][4];
#pragma unroll
    for (int n = 0; n < 8; n++)
#pragma unroll
        for (int r = 0; r < 4; r++) oacc[n][r] = 0.f;

    const int nkb = 2 * qb + 2;
    for (int kb = 0; kb < nkb; kb++) {
        asm volatile("cp.async.wait_group 0;\n" ::: "memory");
        __syncthreads();
        if (kb + 1 < nkb) {
            issue_kv(kb + 1, (kb + 1) & 1);
            asm volatile("cp.async.commit_group;\n" ::: "memory");
        }
        const float (*Kb)[FS_] = Ks[kb & 1];
        const float (*Vb)[FS_] = Vs[kb & 1];

        float sacc[4][4];
#pragma unroll
        for (int n = 0; n < 4; n++)
#pragma unroll
            for (int r = 0; r < 4; r++) sacc[n][r] = 0.f;

#pragma unroll
        for (int kc = 0; kc < 8; kc++)
#pragma unroll
            for (int n = 0; n < 4; n++) {
                float b0 = Kb[n * 8 + gid][kc * 8 + tig];
                float b1 = Kb[n * 8 + gid][kc * 8 + tig + 4];
                mma_tf32(sacc[n][0], sacc[n][1], sacc[n][2], sacc[n][3],
                         qf[kc][0], qf[kc][1], qf[kc][2], qf[kc][3],
                         __float_as_uint(b0), __float_as_uint(b1));
            }

        if (kb >= 2 * qb) {
            const int rg0 = qb * 64 + w * 16 + gid;
#pragma unroll
            for (int n = 0; n < 4; n++) {
                int c = kb * KT_ + n * 8 + 2 * tig;
                if (c     > rg0    ) sacc[n][0] = -1e30f;
                if (c + 1 > rg0    ) sacc[n][1] = -1e30f;
                if (c     > rg0 + 8) sacc[n][2] = -1e30f;
                if (c + 1 > rg0 + 8) sacc[n][3] = -1e30f;
            }
        }

        float mx0 = -1e30f, mx1 = -1e30f;
#pragma unroll
        for (int n = 0; n < 4; n++) {
            mx0 = fmaxf(mx0, fmaxf(sacc[n][0], sacc[n][1]));
            mx1 = fmaxf(mx1, fmaxf(sacc[n][2], sacc[n][3]));
        }
        mx0 = fmaxf(mx0, __shfl_xor_sync(0xffffffffu, mx0, 1));
        mx0 = fmaxf(mx0, __shfl_xor_sync(0xffffffffu, mx0, 2));
        mx1 = fmaxf(mx1, __shfl_xor_sync(0xffffffffu, mx1, 1));
        mx1 = fmaxf(mx1, __shfl_xor_sync(0xffffffffu, mx1, 2));
        float mn0 = fmaxf(m0, mx0), mn1 = fmaxf(m1, mx1);
        float al0 = __expf(m0 - mn0), al1 = __expf(m1 - mn1);
        m0 = mn0; m1 = mn1;

        float sum0 = 0.f, sum1 = 0.f;
#pragma unroll
        for (int n = 0; n < 4; n++) {
            float p0 = tf32r(__expf(sacc[n][0] - mn0));
            float p1 = tf32r(__expf(sacc[n][1] - mn0));
            float p2 = tf32r(__expf(sacc[n][2] - mn1));
            float p3 = tf32r(__expf(sacc[n][3] - mn1));
            sum0 += p0 + p1; sum1 += p2 + p3;
            sacc[n][0] = p0; sacc[n][1] = p1; sacc[n][2] = p2; sacc[n][3] = p3;
        }
        sum0 += __shfl_xor_sync(0xffffffffu, sum0, 1);
        sum0 += __shfl_xor_sync(0xffffffffu, sum0, 2);
        sum1 += __shfl_xor_sync(0xffffffffu, sum1, 1);
        sum1 += __shfl_xor_sync(0xffffffffu, sum1, 2);
        l0 = l0 * al0 + sum0;
        l1 = l1 * al1 + sum1;
#pragma unroll
        for (int n = 0; n < 8; n++) {
            oacc[n][0] *= al0; oacc[n][1] *= al0;
            oacc[n][2] *= al1; oacc[n][3] *= al1;
        }

        const int src0 = (lane & 28) | (tig >> 1);
        const int src1 = src0 + 2;
        const bool odd = (tig & 1);
#pragma unroll
        for (int kc = 0; kc < 4; kc++) {
            float v00 = __shfl_sync(0xffffffffu, sacc[kc][0], src0);
            float v01 = __shfl_sync(0xffffffffu, sacc[kc][1], src0);
            float v10 = __shfl_sync(0xffffffffu, sacc[kc][0], src1);
            float v11 = __shfl_sync(0xffffffffu, sacc[kc][1], src1);
            float v20 = __shfl_sync(0xffffffffu, sacc[kc][2], src0);
            float v21 = __shfl_sync(0xffffffffu, sacc[kc][3], src0);
            float v30 = __shfl_sync(0xffffffffu, sacc[kc][2], src1);
            float v31 = __shfl_sync(0xffffffffu, sacc[kc][3], src1);
            uint32_t a0 = __float_as_uint(odd ? v01 : v00);
            uint32_t a2 = __float_as_uint(odd ? v11 : v10);
            uint32_t a1 = __float_as_uint(odd ? v21 : v20);
            uint32_t a3 = __float_as_uint(odd ? v31 : v30);
#pragma unroll
            for (int n = 0; n < 8; n++) {
                float b0 = Vb[kc * 8 + tig    ][n * 8 + gid];
                float b1 = Vb[kc * 8 + tig + 4][n * 8 + gid];
                mma_tf32(oacc[n][0], oacc[n][1], oacc[n][2], oacc[n][3],
                         a0, a1, a2, a3,
                         __float_as_uint(b0), __float_as_uint(b1));
            }
        }
    }

    const float inv0 = 1.f / l0, inv1 = 1.f / l1;
    const int row0 = qb * 64 + w * 16 + gid;
#pragma unroll
    for (int n = 0; n < 8; n++) {
        int col = h * DH_ + n * 8 + 2 * tig;
        size_t o0 = ((size_t)b * T_ + row0) * E_ + col;
        size_t o1 = ((size_t)b * T_ + row0 + 8) * E_ + col;
        *reinterpret_cast<__half2*>(&g_atth[o0]) =
            __floats2half2_rn(oacc[n][0] * inv0, oacc[n][1] * inv0);
        *reinterpret_cast<__half2*>(&g_atth[o1]) =
            __floats2half2_rn(oacc[n][2] * inv1, oacc[n][3] * inv1);
    }
}

// ---------------------------------------------------------------------------
extern "C" void kernel_launch(void* const* d_in, const int* in_sizes, int n_in,
                              void* d_out, int out_size)
{
    const float* x  = (const float*)d_in[0];
    const float* wi = (const float*)d_in[1];
    const float* bi = (const float*)d_in[2];
    const float* wo = (const float*)d_in[3];
    const float* bo = (const float*)d_in[4];
    const float* wc = (const float*)d_in[5];
    const float* bc = (const float*)d_in[6];
    float* out = (float*)d_out;

    const int M = B_ * T_;  // 8192

    // weight/input prep
    cvt_xh<<<(B_ * T_ * E_ / 4 + 255) / 256, 256>>>(x);
    cvt_w<<<(E_ * E_ + 255) / 256, 256>>>(wi, wc);
    transpose_wo<<<dim3(32, 32), dim3(32, 8)>>>(wo);
    gemm_wcomb_h<<<dim3(E_ / 128, E_ / 128), 256>>>();
    bcomb_k<<<E_ / 8, 256>>>(wc, bo, bc);

    // main chain: QKV proj (fp16) -> attention -> fused projection (fp16)
    gemm_in_h<<<dim3(3 * E_ / 128, M / 256), 256>>>(bi);
    flash_attn<<<dim3(T_ / 64, B_ * H_), 128>>>();
    gemm_fin_h<<<dim3(E_ / 128, M / 256), 256>>>(out);
}

// round 16
// speedup vs baseline: 1.8778x; 1.1481x over previous
#include <cuda_runtime.h>
#include <cuda_fp16.h>
#include <math.h>
#include <stdint.h>

#define B_  8
#define T_  1024
#define E_  1024
#define H_  16
#define DH_ 64

// Scratch (__device__ globals: allocation-free rule; zero-initialized)
__device__ float  g_bcomb[E_];                                       // Wc*bo + bc
__device__ __align__(16) __half g_xh    [(size_t)B_ * T_ * E_];      // 16 MB
__device__ __align__(16) __half g_wih   [(size_t)3 * E_ * E_];       // 6 MB
__device__ __align__(16) __half g_wch   [(size_t)E_ * E_];           // 2 MB
__device__ __align__(16) __half g_woTh  [(size_t)E_ * E_];           // 2 MB
__device__ __align__(16) __half g_qkvh  [(size_t)B_ * T_ * 3 * E_];  // 48 MB
__device__ __align__(16) __half g_atth  [(size_t)B_ * T_ * E_];      // 16 MB
__device__ __align__(16) __half g_wcombh[(size_t)E_ * E_];           // 2 MB

// ---------------------------------------------------------------------------
__device__ __forceinline__ uint32_t sptr(const void* p) {
    return (uint32_t)__cvta_generic_to_shared(p);
}
__device__ __forceinline__ void cpa16(uint32_t dst, const void* src) {
    asm volatile("cp.async.cg.shared.global [%0], [%1], 16;\n" :: "r"(dst), "l"(src));
}
__device__ __forceinline__ void mma_f16(
    float& c0, float& c1, float& c2, float& c3,
    uint32_t a0, uint32_t a1, uint32_t a2, uint32_t a3,
    uint32_t b0, uint32_t b1)
{
    asm volatile(
        "mma.sync.aligned.m16n8k16.row.col.f32.f16.f16.f32 "
        "{%0,%1,%2,%3},{%4,%5,%6,%7},{%8,%9},{%0,%1,%2,%3};"
        : "+f"(c0), "+f"(c1), "+f"(c2), "+f"(c3)
        : "r"(a0), "r"(a1), "r"(a2), "r"(a3), "r"(b0), "r"(b1));
}
__device__ __forceinline__ uint32_t h2u(__half2 h) {
    return *reinterpret_cast<uint32_t*>(&h);
}

// x -> fp16 (rn) --------------------------------------------------------------
__global__ void __launch_bounds__(256) cvt_xh(const float* __restrict__ in) {
    int i = blockIdx.x * blockDim.x + threadIdx.x;
    const int n4 = B_ * T_ * E_ / 4;
    if (i < n4) {
        float4 v = reinterpret_cast<const float4*>(in)[i];
        __half2 h01 = __floats2half2_rn(v.x, v.y);
        __half2 h23 = __floats2half2_rn(v.z, v.w);
        uint2 u;
        u.x = h2u(h01);
        u.y = h2u(h23);
        reinterpret_cast<uint2*>(g_xh)[i] = u;
    }
}

// wi -> half; wc -> half ------------------------------------------------------
__global__ void __launch_bounds__(256) cvt_w(const float* __restrict__ wi,
                                             const float* __restrict__ wc) {
    int i = blockIdx.x * blockDim.x + threadIdx.x;
    const int n_i = 3 * E_ * E_ / 4;
    const int n_o = E_ * E_ / 4;
    const float4* src;
    __half* dsth;
    int j;
    if (i < n_i)             { src = (const float4*)wi; dsth = g_wih; j = i; }
    else if (i < n_i + n_o)  { src = (const float4*)wc; dsth = g_wch; j = i - n_i; }
    else return;
    float4 v = src[j];
    __half2 h01 = __floats2half2_rn(v.x, v.y);
    __half2 h23 = __floats2half2_rn(v.z, v.w);
    uint2 u;
    u.x = h2u(h01);
    u.y = h2u(h23);
    reinterpret_cast<uint2*>(dsth)[j] = u;
}

// 1024x1024 transpose + half convert: g_woTh = half(Wo^T) --------------------
__global__ void __launch_bounds__(256) transpose_wo(const float* __restrict__ wo) {
    __shared__ float t[32][33];
    int x = blockIdx.x * 32 + threadIdx.x;
    int y = blockIdx.y * 32 + threadIdx.y;
#pragma unroll
    for (int i = 0; i < 32; i += 8)
        t[threadIdx.y + i][threadIdx.x] = wo[(size_t)(y + i) * E_ + x];
    __syncthreads();
    x = blockIdx.y * 32 + threadIdx.x;
    y = blockIdx.x * 32 + threadIdx.y;
#pragma unroll
    for (int i = 0; i < 32; i += 8)
        g_woTh[(size_t)(y + i) * E_ + x] = __float2half_rn(t[threadIdx.x][threadIdx.y + i]);
}

// b_comb = Wc * bo + bc (fp32, warp per row) ---------------------------------
__global__ void __launch_bounds__(256) bcomb_k(const float* __restrict__ wc,
                                               const float* __restrict__ bo,
                                               const float* __restrict__ bc) {
    int row  = blockIdx.x * 8 + (threadIdx.x >> 5);
    int lane = threadIdx.x & 31;
    const float* wr = wc + (size_t)row * E_;
    float s = 0.f;
    for (int j = lane; j < E_; j += 32) s += wr[j] * bo[j];
#pragma unroll
    for (int o = 16; o; o >>= 1) s += __shfl_xor_sync(0xffffffffu, s, o);
    if (lane == 0) g_bcomb[row] = bc[row] + s;
}

// ---------------------------------------------------------------------------
// FP16 wcomb GEMM (R14, passing): g_wcombh = half(Wc @ Wo).
// ---------------------------------------------------------------------------
__global__ void __launch_bounds__(256, 2) gemm_wcomb_h()
{
    const __half* A  = g_wch;
    const __half* Bm = g_woTh;
    const int N = E_, K = E_;
    __shared__ __half As[2][128][24];
    __shared__ __half Bs[2][128][24];

    const int tid  = threadIdx.x;
    const int lane = tid & 31;
    const int wid  = tid >> 5;
    const int gid  = lane >> 2;
    const int tig  = lane & 3;
    const int wm   = (wid >> 2) * 64;
    const int wn   = (wid & 3) * 32;
    const int bm   = blockIdx.y * 128;
    const int bn   = blockIdx.x * 128;

    float acc[4][4][4];
#pragma unroll
    for (int mt = 0; mt < 4; mt++)
#pragma unroll
        for (int nt = 0; nt < 4; nt++)
#pragma unroll
            for (int r = 0; r < 4; r++) acc[mt][nt][r] = 0.f;

    auto issue = [&](int k0, int s) {
        int row = tid >> 1;
        int ci  = tid & 1;
        cpa16(sptr(&As[s][row][ci * 8]), A  + (size_t)(bm + row) * K + k0 + ci * 8);
        cpa16(sptr(&Bs[s][row][ci * 8]), Bm + (size_t)(bn + row) * K + k0 + ci * 8);
    };

    issue(0, 0);
    asm volatile("cp.async.commit_group;\n" ::: "memory");

    const int NIT = K / 16;
    for (int it = 0; it < NIT; it++) {
        asm volatile("cp.async.wait_group 0;\n" ::: "memory");
        __syncthreads();
        if (it + 1 < NIT) {
            issue((it + 1) * 16, (it + 1) & 1);
            asm volatile("cp.async.commit_group;\n" ::: "memory");
        }
        const int s = it & 1;
        uint32_t a[4][4], b[4][2];
#pragma unroll
        for (int mt = 0; mt < 4; mt++) {
            int r0 = wm + mt * 16 + gid;
            int r1 = r0 + 8;
            a[mt][0] = *reinterpret_cast<const uint32_t*>(&As[s][r0][2 * tig    ]);
            a[mt][1] = *reinterpret_cast<const uint32_t*>(&As[s][r1][2 * tig    ]);
            a[mt][2] = *reinterpret_cast<const uint32_t*>(&As[s][r0][2 * tig + 8]);
            a[mt][3] = *reinterpret_cast<const uint32_t*>(&As[s][r1][2 * tig + 8]);
        }
#pragma unroll
        for (int nt = 0; nt < 4; nt++) {
            int c0i = wn + nt * 8 + gid;
            b[nt][0] = *reinterpret_cast<const uint32_t*>(&Bs[s][c0i][2 * tig    ]);
            b[nt][1] = *reinterpret_cast<const uint32_t*>(&Bs[s][c0i][2 * tig + 8]);
        }
#pragma unroll
        for (int mt = 0; mt < 4; mt++)
#pragma unroll
            for (int nt = 0; nt < 4; nt++)
                mma_f16(acc[mt][nt][0], acc[mt][nt][1], acc[mt][nt][2], acc[mt][nt][3],
                        a[mt][0], a[mt][1], a[mt][2], a[mt][3], b[nt][0], b[nt][1]);
    }

#pragma unroll
    for (int mt = 0; mt < 4; mt++) {
#pragma unroll
        for (int nt = 0; nt < 4; nt++) {
            int row = bm + wm + mt * 16 + gid;
            int col = bn + wn + nt * 8 + tig * 2;
            *reinterpret_cast<__half2*>(&g_wcombh[(size_t)row * N + col]) =
                __floats2half2_rn(acc[mt][nt][0], acc[mt][nt][1]);
            *reinterpret_cast<__half2*>(&g_wcombh[(size_t)(row + 8) * N + col]) =
                __floats2half2_rn(acc[mt][nt][2], acc[mt][nt][3]);
        }
    }
}

// ---------------------------------------------------------------------------
// Big FP16 GEMM, 3-stage pipeline (R14, passing). Ch selects half output
// (qkv) vs float output (final).
// ---------------------------------------------------------------------------
__device__ __forceinline__ void gemm_f16_big3(
    const __half* __restrict__ A, const __half* __restrict__ Bm,
    const float* __restrict__ bias, float* __restrict__ Cf,
    __half* __restrict__ Ch, int N, int K)
{
    __shared__ __half As[3][256][16];
    __shared__ __half Bs[3][128][16];

    const int tid  = threadIdx.x;
    const int lane = tid & 31;
    const int wid  = tid >> 5;
    const int gid  = lane >> 2;
    const int tig  = lane & 3;
    const int wm   = (wid >> 1) * 64;
    const int wn   = (wid & 1) * 64;
    const int bm   = blockIdx.y * 256;
    const int bn   = blockIdx.x * 128;

    float acc[4][8][4];
#pragma unroll
    for (int mt = 0; mt < 4; mt++)
#pragma unroll
        for (int nt = 0; nt < 8; nt++)
#pragma unroll
            for (int r = 0; r < 4; r++) acc[mt][nt][r] = 0.f;

    auto issue = [&](int k0, int s) {
#pragma unroll
        for (int i = 0; i < 2; i++) {
            int idx = tid + i * 256;
            int row = idx >> 1;
            int ci  = idx & 1;
            cpa16(sptr(&As[s][row][(ci ^ (row & 1)) * 8]),
                  A + (size_t)(bm + row) * K + k0 + ci * 8);
        }
        {
            int row = tid >> 1;
            int ci  = tid & 1;
            cpa16(sptr(&Bs[s][row][(ci ^ (row & 1)) * 8]),
                  Bm + (size_t)(bn + row) * K + k0 + ci * 8);
        }
    };

    issue(0, 0);
    asm volatile("cp.async.commit_group;\n" ::: "memory");
    issue(16, 1);
    asm volatile("cp.async.commit_group;\n" ::: "memory");

    const int NIT = K / 16;
    int sc = 0;
    for (int it = 0; it < NIT; it++) {
        if (it + 1 < NIT) {
            asm volatile("cp.async.wait_group 1;\n" ::: "memory");
        } else {
            asm volatile("cp.async.wait_group 0;\n" ::: "memory");
        }
        __syncthreads();
        if (it + 2 < NIT) {
            int s2 = sc + 2; if (s2 >= 3) s2 -= 3;
            issue((it + 2) * 16, s2);
            asm volatile("cp.async.commit_group;\n" ::: "memory");
        }

        uint32_t a[4][4], b[8][2];
#pragma unroll
        for (int mt = 0; mt < 4; mt++) {
            int r0 = wm + mt * 16 + gid;
            int r1 = r0 + 8;
            int p  = (r0 & 1) * 8;
            a[mt][0] = *reinterpret_cast<const uint32_t*>(&As[sc][r0][p       + 2 * tig]);
            a[mt][1] = *reinterpret_cast<const uint32_t*>(&As[sc][r1][p       + 2 * tig]);
            a[mt][2] = *reinterpret_cast<const uint32_t*>(&As[sc][r0][(8 - p) + 2 * tig]);
            a[mt][3] = *reinterpret_cast<const uint32_t*>(&As[sc][r1][(8 - p) + 2 * tig]);
        }
#pragma unroll
        for (int nt = 0; nt < 8; nt++) {
            int c0i = wn + nt * 8 + gid;
            int p   = (c0i & 1) * 8;
            b[nt][0] = *reinterpret_cast<const uint32_t*>(&Bs[sc][c0i][p       + 2 * tig]);
            b[nt][1] = *reinterpret_cast<const uint32_t*>(&Bs[sc][c0i][(8 - p) + 2 * tig]);
        }
#pragma unroll
        for (int mt = 0; mt < 4; mt++)
#pragma unroll
            for (int nt = 0; nt < 8; nt++)
                mma_f16(acc[mt][nt][0], acc[mt][nt][1], acc[mt][nt][2], acc[mt][nt][3],
                        a[mt][0], a[mt][1], a[mt][2], a[mt][3], b[nt][0], b[nt][1]);

        sc = (sc == 2) ? 0 : sc + 1;
    }

#pragma unroll
    for (int mt = 0; mt < 4; mt++) {
#pragma unroll
        for (int nt = 0; nt < 8; nt++) {
            int row = bm + wm + mt * 16 + gid;
            int col = bn + wn + nt * 8 + tig * 2;
            float bv0 = bias[col], bv1 = bias[col + 1];
            float v0 = acc[mt][nt][0] + bv0;
            float v1 = acc[mt][nt][1] + bv1;
            float v2 = acc[mt][nt][2] + bv0;
            float v3 = acc[mt][nt][3] + bv1;
            if (Ch) {
                *reinterpret_cast<__half2*>(&Ch[(size_t)row * N + col]) =
                    __floats2half2_rn(v0, v1);
                *reinterpret_cast<__half2*>(&Ch[(size_t)(row + 8) * N + col]) =
                    __floats2half2_rn(v2, v3);
            } else {
                *reinterpret_cast<float2*>(Cf + (size_t)row * N + col) = make_float2(v0, v1);
                *reinterpret_cast<float2*>(Cf + (size_t)(row + 8) * N + col) = make_float2(v2, v3);
            }
        }
    }
}

__global__ void __launch_bounds__(256, 1) gemm_in_h(const float* __restrict__ bi) {
    gemm_f16_big3(g_xh, g_wih, bi, nullptr, g_qkvh, 3 * E_, E_);
}
__global__ void __launch_bounds__(256, 1) gemm_fin_h(float* __restrict__ out) {
    gemm_f16_big3(g_atth, g_wcombh, g_bcomb, out, nullptr, E_, E_);
}

// ---------------------------------------------------------------------------
// FP16 tensor-core causal flash attention, cp.async pipelined.
// grid (T/64, B*H) qb-reversed, 128 threads (4 warps), warp = 16 query rows.
// KV tile 32, [key][d] half smem, stride 72 halves (36 words): K/Q half2
// frag loads hit banks (4g+t) mod 32 = permutation. V B-frags built from
// paired u16 loads. P C-frag -> A-frag is a direct half2 pack (no shuffles).
// Smem 2*(2*32*72)*2 = 18,432 B.
// ---------------------------------------------------------------------------
#define KT_ 32
#define FSH 72

__global__ void __launch_bounds__(128, 3) flash_attn()
{
    __shared__ __align__(16) __half Ks[2][KT_][FSH];
    __shared__ __align__(16) __half Vs[2][KT_][FSH];

    const __half* qkv = g_qkvh;
    const int tid  = threadIdx.x;
    const int lane = tid & 31;
    const int w    = tid >> 5;
    const int gid  = lane >> 2;
    const int tig  = lane & 3;
    const int qb   = gridDim.x - 1 - blockIdx.x;
    const int b    = blockIdx.y >> 4;
    const int h    = blockIdx.y & 15;
    const size_t base = (size_t)b * T_ * 3 * E_ + (size_t)h * DH_;

    // ---- stage Q (64x64 half) into Ks[0..1] ----
#pragma unroll
    for (int i = 0; i < 4; i++) {
        int idx = tid + i * 128;          // 0..511
        int row = idx >> 3;               // 0..63
        int c8  = (idx & 7) * 8;          // 0..56 halves
        cpa16(sptr(&Ks[row >> 5][row & 31][c8]),
              qkv + base + (size_t)(qb * 64 + row) * 3 * E_ + c8);
    }
    asm volatile("cp.async.commit_group;\n" ::: "memory");
    asm volatile("cp.async.wait_group 0;\n" ::: "memory");
    __syncthreads();

    // ---- Q fragments (half2, scale 1/8 folded: exact pow2) ----
    const __half2 s8 = __float2half2_rn(0.125f);
    uint32_t qf[4][4];
    {
        const int r0 = w * 16 + gid;
        const int r1 = r0 + 8;
#pragma unroll
        for (int kc = 0; kc < 4; kc++) {
            __half2 t0 = *reinterpret_cast<const __half2*>(&Ks[r0 >> 5][r0 & 31][kc * 16 + 2 * tig    ]);
            __half2 t1 = *reinterpret_cast<const __half2*>(&Ks[r1 >> 5][r1 & 31][kc * 16 + 2 * tig    ]);
            __half2 t2 = *reinterpret_cast<const __half2*>(&Ks[r0 >> 5][r0 & 31][kc * 16 + 2 * tig + 8]);
            __half2 t3 = *reinterpret_cast<const __half2*>(&Ks[r1 >> 5][r1 & 31][kc * 16 + 2 * tig + 8]);
            qf[kc][0] = h2u(__hmul2(t0, s8));
            qf[kc][1] = h2u(__hmul2(t1, s8));
            qf[kc][2] = h2u(__hmul2(t2, s8));
            qf[kc][3] = h2u(__hmul2(t3, s8));
        }
    }
    __syncthreads();   // everyone done reading Q; buffers reusable

    auto issue_kv = [&](int kb, int s) {
#pragma unroll
        for (int i = 0; i < 2; i++) {
            int idx = tid + i * 128;      // 0..255
            int row = idx >> 3;           // 0..31
            int c8  = (idx & 7) * 8;
            size_t tok = base + (size_t)(kb * KT_ + row) * 3 * E_;
            cpa16(sptr(&Ks[s][row][c8]), qkv + tok + E_ + c8);
            cpa16(sptr(&Vs[s][row][c8]), qkv + tok + 2 * E_ + c8);
        }
    };

    issue_kv(0, 0);
    asm volatile("cp.async.commit_group;\n" ::: "memory");

    float m0 = -1e30f, m1 = -1e30f, l0 = 0.f, l1 = 0.f;
    float oacc[8][4];
#pragma unroll
    for (int n = 0; n < 8; n++)
#pragma unroll
        for (int r = 0; r < 4; r++) oacc[n][r] = 0.f;

    const int nkb = 2 * qb + 2;          // causal: KV tiles 0 .. 2qb+1
    for (int kb = 0; kb < nkb; kb++) {
        asm volatile("cp.async.wait_group 0;\n" ::: "memory");
        __syncthreads();
        if (kb + 1 < nkb) {
            issue_kv(kb + 1, (kb + 1) & 1);
            asm volatile("cp.async.commit_group;\n" ::: "memory");
        }
        const __half (*Kb)[FSH] = Ks[kb & 1];
        const __half (*Vb)[FSH] = Vs[kb & 1];

        // ---- S = Q K^T : 4 n-tiles (32 keys) x 4 k-steps (d=64) ----
        float sacc[4][4];
#pragma unroll
        for (int n = 0; n < 4; n++)
#pragma unroll
            for (int r = 0; r < 4; r++) sacc[n][r] = 0.f;

#pragma unroll
        for (int kc = 0; kc < 4; kc++)
#pragma unroll
            for (int n = 0; n < 4; n++) {
                uint32_t b0 = *reinterpret_cast<const uint32_t*>(
                    &Kb[n * 8 + gid][kc * 16 + 2 * tig    ]);
                uint32_t b1 = *reinterpret_cast<const uint32_t*>(
                    &Kb[n * 8 + gid][kc * 16 + 2 * tig + 8]);
                mma_f16(sacc[n][0], sacc[n][1], sacc[n][2], sacc[n][3],
                        qf[kc][0], qf[kc][1], qf[kc][2], qf[kc][3], b0, b1);
            }

        // ---- causal mask ----
        if (kb >= 2 * qb) {
            const int rg0 = qb * 64 + w * 16 + gid;
#pragma unroll
            for (int n = 0; n < 4; n++) {
                int c = kb * KT_ + n * 8 + 2 * tig;
                if (c     > rg0    ) sacc[n][0] = -1e30f;
                if (c + 1 > rg0    ) sacc[n][1] = -1e30f;
                if (c     > rg0 + 8) sacc[n][2] = -1e30f;
                if (c + 1 > rg0 + 8) sacc[n][3] = -1e30f;
            }
        }

        // ---- online softmax (rows gid / gid+8), quad-lane reduce ----
        float mx0 = -1e30f, mx1 = -1e30f;
#pragma unroll
        for (int n = 0; n < 4; n++) {
            mx0 = fmaxf(mx0, fmaxf(sacc[n][0], sacc[n][1]));
            mx1 = fmaxf(mx1, fmaxf(sacc[n][2], sacc[n][3]));
        }
        mx0 = fmaxf(mx0, __shfl_xor_sync(0xffffffffu, mx0, 1));
        mx0 = fmaxf(mx0, __shfl_xor_sync(0xffffffffu, mx0, 2));
        mx1 = fmaxf(mx1, __shfl_xor_sync(0xffffffffu, mx1, 1));
        mx1 = fmaxf(mx1, __shfl_xor_sync(0xffffffffu, mx1, 2));
        float mn0 = fmaxf(m0, mx0), mn1 = fmaxf(m1, mx1);
        float al0 = __expf(m0 - mn0), al1 = __expf(m1 - mn1);
        m0 = mn0; m1 = mn1;

        // P packed directly into A-fragment halves (no shuffles needed)
        uint32_t pa[4], pc[4];
        float sum0 = 0.f, sum1 = 0.f;
#pragma unroll
        for (int n = 0; n < 4; n++) {
            __half2 hp0 = __floats2half2_rn(__expf(sacc[n][0] - mn0),
                                            __expf(sacc[n][1] - mn0));
            __half2 hp1 = __floats2half2_rn(__expf(sacc[n][2] - mn1),
                                            __expf(sacc[n][3] - mn1));
            float2 f0 = __half22float2(hp0);
            float2 f1 = __half22float2(hp1);
            sum0 += f0.x + f0.y;
            sum1 += f1.x + f1.y;
            pa[n] = h2u(hp0);
            pc[n] = h2u(hp1);
        }
        sum0 += __shfl_xor_sync(0xffffffffu, sum0, 1);
        sum0 += __shfl_xor_sync(0xffffffffu, sum0, 2);
        sum1 += __shfl_xor_sync(0xffffffffu, sum1, 1);
        sum1 += __shfl_xor_sync(0xffffffffu, sum1, 2);
        l0 = l0 * al0 + sum0;
        l1 = l1 * al1 + sum1;
#pragma unroll
        for (int n = 0; n < 8; n++) {
            oacc[n][0] *= al0; oacc[n][1] *= al0;
            oacc[n][2] *= al1; oacc[n][3] *= al1;
        }

        // ---- O += P V : 2 k-steps (32 keys), 8 d-tiles ----
#pragma unroll
        for (int kc = 0; kc < 2; kc++) {
            uint32_t a0 = pa[2 * kc];
            uint32_t a1 = pc[2 * kc];
            uint32_t a2 = pa[2 * kc + 1];
            uint32_t a3 = pc[2 * kc + 1];
            const int k0 = kc * 16 + 2 * tig;
#pragma unroll
            for (int n = 0; n < 8; n++) {
                int colh = n * 8 + gid;
                uint32_t b0 = h2u(__halves2half2(Vb[k0    ][colh], Vb[k0 + 1][colh]));
                uint32_t b1 = h2u(__halves2half2(Vb[k0 + 8][colh], Vb[k0 + 9][colh]));
                mma_f16(oacc[n][0], oacc[n][1], oacc[n][2], oacc[n][3],
                        a0, a1, a2, a3, b0, b1);
            }
        }
    }

    // ---- epilogue: normalize, write att as fp16 half2 [B,T,E] ----
    const float inv0 = 1.f / l0, inv1 = 1.f / l1;
    const int row0 = qb * 64 + w * 16 + gid;
#pragma unroll
    for (int n = 0; n < 8; n++) {
        int col = h * DH_ + n * 8 + 2 * tig;
        size_t o0 = ((size_t)b * T_ + row0) * E_ + col;
        size_t o1 = ((size_t)b * T_ + row0 + 8) * E_ + col;
        *reinterpret_cast<__half2*>(&g_atth[o0]) =
            __floats2half2_rn(oacc[n][0] * inv0, oacc[n][1] * inv0);
        *reinterpret_cast<__half2*>(&g_atth[o1]) =
            __floats2half2_rn(oacc[n][2] * inv1, oacc[n][3] * inv1);
    }
}

// ---------------------------------------------------------------------------
extern "C" void kernel_launch(void* const* d_in, const int* in_sizes, int n_in,
                              void* d_out, int out_size)
{
    const float* x  = (const float*)d_in[0];
    const float* wi = (const float*)d_in[1];
    const float* bi = (const float*)d_in[2];
    const float* wo = (const float*)d_in[3];
    const float* bo = (const float*)d_in[4];
    const float* wc = (const float*)d_in[5];
    const float* bc = (const float*)d_in[6];
    float* out = (float*)d_out;

    const int M = B_ * T_;  // 8192

    // weight/input prep
    cvt_xh<<<(B_ * T_ * E_ / 4 + 255) / 256, 256>>>(x);
    cvt_w<<<(E_ * E_ + 255) / 256, 256>>>(wi, wc);
    transpose_wo<<<dim3(32, 32), dim3(32, 8)>>>(wo);
    gemm_wcomb_h<<<dim3(E_ / 128, E_ / 128), 256>>>();
    bcomb_k<<<E_ / 8, 256>>>(wc, bo, bc);

    // main chain: QKV proj (fp16) -> fp16 attention -> fused projection (fp16)
    gemm_in_h<<<dim3(3 * E_ / 128, M / 256), 256>>>(bi);
    flash_attn<<<dim3(T_ / 64, B_ * H_), 128>>>();
    gemm_fin_h<<<dim3(E_ / 128, M / 256), 256>>>(out);
}